// round 2
// baseline (speedup 1.0000x reference)
#include <cuda_runtime.h>

#define B_   128
#define NT   197
#define HH   12
#define HD   64
#define DIM_ 768
#define MTOK (B_ * NT)          // 25216 = 197 * 128 (exact tiles!)

#define KS_STRIDE 65
#define SC_STRIDE 198

// Align-up helper (in floats, to 16B = 4 floats)
#define AL4(x) (((x) + 3) & ~3)

// SMEM region offsets (floats). Vs first (float4-accessed), rest padded to 16B.
#define OFF_VS   0
#define OFF_KS   AL4(OFF_VS + NT * HD)          // 12608
#define OFF_QS   AL4(OFF_KS + NT * KS_STRIDE)   // 12608+12805 -> 25416
#define OFF_SC   AL4(OFF_QS + 32 * HD)          // +2048
#define OFF_INV  AL4(OFF_SC + 32 * SC_STRIDE)   // +6336
#define SMEM_FLOATS (OFF_INV + 32)

// ---------------- scratch (__device__ globals; no allocation allowed) ----------------
__device__ float g_qkv[(long long)MTOK * 2304];   // 232 MB
__device__ float g_ao [(long long)MTOK * DIM_];   // 77 MB
__device__ float g_bias[HH * NT * NT];            // 1.86 MB

// ---------------- bias gather: bias[h][i][j] = table[idx[i][j]][h] ----------------
__global__ void bias_kernel(const float* __restrict__ table,
                            const int*   __restrict__ idx,
                            float* __restrict__ out)
{
    int t = blockIdx.x * blockDim.x + threadIdx.x;
    const int TOT = HH * NT * NT;
    if (t < TOT) {
        int ij = t % (NT * NT);
        int h  = t / (NT * NT);
        out[t] = table[idx[ij] * HH + h];
    }
}

// ---------------- tiled SGEMM with bias: C[M,Nn] = A[M,K] * W[Nn,K]^T + bias ----------------
// BM=BN=128, BK=16, 256 threads, 8x8 register tile. M,Nn multiples of 128; K multiple of 16.
__global__ __launch_bounds__(256) void gemm_bias_kernel(
    const float* __restrict__ A, const float* __restrict__ W,
    const float* __restrict__ bias, float* __restrict__ C,
    int M, int Nn, int K)
{
    __shared__ float As[16][128];
    __shared__ float Ws[16][128];
    const int tid = threadIdx.x;
    const int m0 = blockIdx.y * 128;
    const int n0 = blockIdx.x * 128;
    const int tx = tid & 15;
    const int ty = tid >> 4;

    float acc[8][8];
#pragma unroll
    for (int i = 0; i < 8; i++)
#pragma unroll
        for (int j = 0; j < 8; j++) acc[i][j] = 0.f;

    for (int k0 = 0; k0 < K; k0 += 16) {
#pragma unroll
        for (int l = 0; l < 2; l++) {
            int idx = tid + l * 256;
            int row = idx >> 2;
            int kq  = (idx & 3) << 2;
            float4 va = *(const float4*)(A + (size_t)(m0 + row) * K + k0 + kq);
            As[kq + 0][row] = va.x; As[kq + 1][row] = va.y;
            As[kq + 2][row] = va.z; As[kq + 3][row] = va.w;
            float4 vw = *(const float4*)(W + (size_t)(n0 + row) * K + k0 + kq);
            Ws[kq + 0][row] = vw.x; Ws[kq + 1][row] = vw.y;
            Ws[kq + 2][row] = vw.z; Ws[kq + 3][row] = vw.w;
        }
        __syncthreads();
#pragma unroll
        for (int kk = 0; kk < 16; kk++) {
            float a[8], w[8];
            *(float4*)&a[0] = *(const float4*)&As[kk][ty * 8];
            *(float4*)&a[4] = *(const float4*)&As[kk][ty * 8 + 4];
            *(float4*)&w[0] = *(const float4*)&Ws[kk][tx * 8];
            *(float4*)&w[4] = *(const float4*)&Ws[kk][tx * 8 + 4];
#pragma unroll
            for (int i = 0; i < 8; i++)
#pragma unroll
                for (int j = 0; j < 8; j++) acc[i][j] += a[i] * w[j];
        }
        __syncthreads();
    }

    float bl[8];
    *(float4*)&bl[0] = *(const float4*)(bias + n0 + tx * 8);
    *(float4*)&bl[4] = *(const float4*)(bias + n0 + tx * 8 + 4);
#pragma unroll
    for (int i = 0; i < 8; i++) {
        size_t off = (size_t)(m0 + ty * 8 + i) * Nn + n0 + tx * 8;
        float4 o0 = make_float4(acc[i][0] + bl[0], acc[i][1] + bl[1],
                                acc[i][2] + bl[2], acc[i][3] + bl[3]);
        float4 o1 = make_float4(acc[i][4] + bl[4], acc[i][5] + bl[5],
                                acc[i][6] + bl[6], acc[i][7] + bl[7]);
        *(float4*)(C + off)     = o0;
        *(float4*)(C + off + 4) = o1;
    }
}

// ---------------- fused attention: one CTA per (b,h); K,V fully in SMEM ----------------
__global__ __launch_bounds__(256) void attn_kernel(
    const float* __restrict__ qkv, const float* __restrict__ bias,
    float* __restrict__ ao)
{
    extern __shared__ float sm[];
    float* Vs  = sm + OFF_VS;               // [197][64]  (float4 stores -> first, 16B aligned)
    float* Ks  = sm + OFF_KS;               // [197][65]  (pad -> conflict-free col reads)
    float* Qs  = sm + OFF_QS;               // [32][64]
    float* Sc  = sm + OFF_SC;               // [32][198]
    float* Inv = sm + OFF_INV;              // [32]

    const int b = blockIdx.x / HH;
    const int h = blockIdx.x % HH;
    const int tid = threadIdx.x;
    const float scale = 0.125f;             // 64^-0.5
    const float* base = qkv + (size_t)b * NT * 2304 + h * 64;

    // load K, V (float4 from global)
    for (int p = tid; p < NT * 16; p += 256) {
        int n = p >> 4, f = (p & 15) << 2;
        float4 kv = *(const float4*)(base + (size_t)n * 2304 + 768 + f);
        Ks[n * KS_STRIDE + f + 0] = kv.x; Ks[n * KS_STRIDE + f + 1] = kv.y;
        Ks[n * KS_STRIDE + f + 2] = kv.z; Ks[n * KS_STRIDE + f + 3] = kv.w;
        float4 vv = *(const float4*)(base + (size_t)n * 2304 + 1536 + f);
        *(float4*)(Vs + n * HD + f) = vv;
    }
    const float* biasH = bias + (size_t)h * NT * NT;
    const int ty = tid >> 5, tx = tid & 31;
    __syncthreads();

    for (int qt = 0; qt < 7; qt++) {
        const int r0 = qt * 32;
        const int rows = min(32, NT - r0);

        // load Q tile, pre-scaled (scalar stores)
        for (int p = tid; p < 32 * 16; p += 256) {
            int n = p >> 4, f = (p & 15) << 2;
            if (n < rows) {
                float4 qv = *(const float4*)(base + (size_t)(r0 + n) * 2304 + f);
                Qs[n * HD + f + 0] = qv.x * scale; Qs[n * HD + f + 1] = qv.y * scale;
                Qs[n * HD + f + 2] = qv.z * scale; Qs[n * HD + f + 3] = qv.w * scale;
            } else {
                Qs[n * HD + f + 0] = 0.f; Qs[n * HD + f + 1] = 0.f;
                Qs[n * HD + f + 2] = 0.f; Qs[n * HD + f + 3] = 0.f;
            }
        }
        __syncthreads();

        // scores: warp ty owns rows ty*4..ty*4+3; lane tx owns cols tx+32*ci
        {
            int  cc[7]; bool cv[7];
#pragma unroll
            for (int ci = 0; ci < 7; ci++) {
                int c = tx + 32 * ci; cv[ci] = (c < NT); cc[ci] = cv[ci] ? c : (NT - 1);
            }
            float acc[4][7];
#pragma unroll
            for (int i = 0; i < 4; i++) {
                int r = ty * 4 + i;
#pragma unroll
                for (int ci = 0; ci < 7; ci++)
                    acc[i][ci] = (r < rows && cv[ci])
                               ? biasH[(size_t)(r0 + r) * NT + cc[ci]] : 0.f;
            }
#pragma unroll 4
            for (int d = 0; d < HD; d++) {
                float q0 = Qs[(ty * 4 + 0) * HD + d];
                float q1 = Qs[(ty * 4 + 1) * HD + d];
                float q2 = Qs[(ty * 4 + 2) * HD + d];
                float q3 = Qs[(ty * 4 + 3) * HD + d];
#pragma unroll
                for (int ci = 0; ci < 7; ci++) {
                    float kv = Ks[cc[ci] * KS_STRIDE + d];
                    acc[0][ci] += q0 * kv;
                    acc[1][ci] += q1 * kv;
                    acc[2][ci] += q2 * kv;
                    acc[3][ci] += q3 * kv;
                }
            }
#pragma unroll
            for (int i = 0; i < 4; i++) {
                int r = ty * 4 + i;
                if (r < rows) {
#pragma unroll
                    for (int ci = 0; ci < 7; ci++)
                        if (cv[ci]) Sc[r * SC_STRIDE + cc[ci]] = acc[i][ci];
                }
            }
        }
        __syncthreads();

        // softmax per row (warp-parallel over 197 cols)
#pragma unroll
        for (int i = 0; i < 4; i++) {
            int r = ty * 4 + i;
            if (r < rows) {
                float m = -3.4e38f;
                for (int c = tx; c < NT; c += 32) m = fmaxf(m, Sc[r * SC_STRIDE + c]);
#pragma unroll
                for (int o = 16; o > 0; o >>= 1) m = fmaxf(m, __shfl_xor_sync(0xffffffffu, m, o));
                float s = 0.f;
                for (int c = tx; c < NT; c += 32) {
                    float e = __expf(Sc[r * SC_STRIDE + c] - m);
                    Sc[r * SC_STRIDE + c] = e;
                    s += e;
                }
#pragma unroll
                for (int o = 16; o > 0; o >>= 1) s += __shfl_xor_sync(0xffffffffu, s, o);
                if (tx == 0) Inv[r] = 1.f / s;
            }
        }
        __syncthreads();

        // AV: out[r][d] = sum_c P[r][c] * V[c][d]; lane tx owns d = tx, tx+32
        {
            float o[4][2] = {};
            for (int c = 0; c < NT; c++) {
                float v0 = Vs[c * HD + tx];
                float v1 = Vs[c * HD + tx + 32];
#pragma unroll
                for (int i = 0; i < 4; i++) {
                    float s = Sc[(ty * 4 + i) * SC_STRIDE + c];
                    o[i][0] += s * v0;
                    o[i][1] += s * v1;
                }
            }
#pragma unroll
            for (int i = 0; i < 4; i++) {
                int r = ty * 4 + i;
                if (r < rows) {
                    float inv = Inv[r];
                    size_t off = ((size_t)b * NT + r0 + r) * DIM_ + h * 64;
                    ao[off + tx]      = o[i][0] * inv;
                    ao[off + tx + 32] = o[i][1] * inv;
                }
            }
        }
        __syncthreads();
    }
}

// ---------------- launch ----------------
extern "C" void kernel_launch(void* const* d_in, const int* in_sizes, int n_in,
                              void* d_out, int out_size)
{
    const float* x      = (const float*)d_in[0];
    const float* qkv_w  = (const float*)d_in[1];
    const float* qkv_b  = (const float*)d_in[2];
    const float* proj_w = (const float*)d_in[3];
    const float* proj_b = (const float*)d_in[4];
    const float* table  = (const float*)d_in[5];
    const int*   relidx = (const int*)d_in[6];
    float* out = (float*)d_out;

    float *p_qkv, *p_ao, *p_bias;
    cudaGetSymbolAddress((void**)&p_qkv,  g_qkv);
    cudaGetSymbolAddress((void**)&p_ao,   g_ao);
    cudaGetSymbolAddress((void**)&p_bias, g_bias);

    const int smem_att = SMEM_FLOATS * 4;
    cudaFuncSetAttribute(attn_kernel, cudaFuncAttributeMaxDynamicSharedMemorySize, smem_att);

    bias_kernel<<<(HH * NT * NT + 255) / 256, 256>>>(table, relidx, p_bias);

    dim3 g1(2304 / 128, MTOK / 128);
    gemm_bias_kernel<<<g1, 256>>>(x, qkv_w, qkv_b, p_qkv, MTOK, 2304, DIM_);

    attn_kernel<<<B_ * HH, 256, smem_att>>>(p_qkv, p_bias, p_ao);

    dim3 g2(DIM_ / 128, MTOK / 128);
    gemm_bias_kernel<<<g2, 256>>>(p_ao, proj_w, proj_b, out, MTOK, DIM_, DIM_);
}

// round 4
// speedup vs baseline: 1.7078x; 1.7078x over previous
#include <cuda_runtime.h>
#include <cuda_fp16.h>
#include <cstdint>

#define B_   128
#define NT   197
#define HH   12
#define HD   64
#define DIM_ 768
#define MTOK (B_ * NT)          // 25216 = 197*128

#define KS_STRIDE 65
#define SC_STRIDE 198
#define AL4(x) (((x) + 3) & ~3)
#define OFF_VS   0
#define OFF_KS   AL4(OFF_VS + NT * HD)
#define OFF_QS   AL4(OFF_KS + NT * KS_STRIDE)
#define OFF_SC   AL4(OFF_QS + 32 * HD)
#define OFF_INV  AL4(OFF_SC + 32 * SC_STRIDE)
#define SMEM_FLOATS (OFF_INV + 32)

// ---------------- scratch ----------------
__device__ float  g_qkv [(long long)MTOK * 2304];
__device__ __half g_xhi [(long long)MTOK * DIM_];
__device__ __half g_xlo [(long long)MTOK * DIM_];
__device__ __half g_aohi[(long long)MTOK * DIM_];
__device__ __half g_aolo[(long long)MTOK * DIM_];
__device__ __half g_qwhi[2304 * DIM_];
__device__ __half g_qwlo[2304 * DIM_];
__device__ __half g_pwhi[DIM_ * DIM_];
__device__ __half g_pwlo[DIM_ * DIM_];
__device__ float  g_bias[HH * NT * NT];

// ---------------- helpers ----------------
__device__ __forceinline__ uint32_t smem_u32(const void* p) {
    uint32_t a;
    asm("{ .reg .u64 t; cvta.to.shared.u64 t, %1; cvt.u32.u64 %0, t; }" : "=r"(a) : "l"(p));
    return a;
}

#define CPA16(dst, src)   asm volatile("cp.async.cg.shared.global [%0], [%1], 16;" :: "r"(dst), "l"(src) : "memory")
#define CPA_COMMIT()      asm volatile("cp.async.commit_group;" ::: "memory")
#define CPA_WAIT(n)       asm volatile("cp.async.wait_group %0;" :: "n"(n) : "memory")

#define LDSM_X4(r0, r1, r2, r3, addr) \
    asm volatile("ldmatrix.sync.aligned.m8n8.x4.shared.b16 {%0,%1,%2,%3}, [%4];" \
        : "=r"(r0), "=r"(r1), "=r"(r2), "=r"(r3) : "r"(addr))

#define MMA16816(d, a, b0, b1) \
    asm volatile("mma.sync.aligned.m16n8k16.row.col.f32.f16.f16.f32 " \
        "{%0,%1,%2,%3}, {%4,%5,%6,%7}, {%8,%9}, {%0,%1,%2,%3};" \
        : "+f"((d)[0]), "+f"((d)[1]), "+f"((d)[2]), "+f"((d)[3]) \
        : "r"((a)[0]), "r"((a)[1]), "r"((a)[2]), "r"((a)[3]), "r"(b0), "r"(b1))

// swizzled tile offset: tile = 128 rows x 32 halves (64B/row), chunk = 16B unit
__device__ __forceinline__ uint32_t sw_off(int row, int chunk) {
    return (uint32_t)(row * 64 + ((chunk ^ ((row >> 1) & 3)) << 4));
}

static __device__ __forceinline__ void h_split(float v, __half& hi, __half& lo) {
    hi = __float2half_rn(v);
    lo = __float2half_rn(v - __half2float(hi));
}

// ---------------- elementwise fp16 split ----------------
__global__ void split_kernel(const float* __restrict__ in,
                             __half* __restrict__ hi, __half* __restrict__ lo, int n)
{
    int t = blockIdx.x * 256 + threadIdx.x;
    if (t < n) {
        __half h, l;
        h_split(in[t], h, l);
        hi[t] = h; lo[t] = l;
    }
}

// ---------------- bias gather ----------------
__global__ void bias_kernel(const float* __restrict__ table,
                            const int*   __restrict__ idx,
                            float* __restrict__ out)
{
    int t = blockIdx.x * blockDim.x + threadIdx.x;
    if (t < HH * NT * NT) {
        int ij = t % (NT * NT);
        int h  = t / (NT * NT);
        out[t] = table[idx[ij] * HH + h];
    }
}

// ---------------- 3xFP16 mma.sync GEMM: C[128 x 128] per CTA, K=768 ----------------
// C = A[M,768] * W[N,768]^T + bias, via (Ah+Al)(Wh+Wl) ~= AhWh + AhWl + AlWh
#define GK     768
#define NCHUNK 24
#define TILEB  8192                   // 128 x 32 halves
#define STAGEB (4 * TILEB)            // Ahi, Alo, Bhi, Blo
#define GSMEM  (2 * STAGEB)           // 64 KB

static __device__ __forceinline__ void load_stage(
    uint32_t sb, const __half* __restrict__ Ahi, const __half* __restrict__ Alo,
    const __half* __restrict__ Whi, const __half* __restrict__ Wlo,
    int m0, int n0, int k0, int tid)
{
#pragma unroll
    for (int j = 0; j < 2; j++) {
        int id = tid + (j << 8);           // 0..511
        int row = id >> 2, c = id & 3;
        uint32_t o = sw_off(row, c);
        size_t ga = (size_t)(m0 + row) * GK + k0 + c * 8;
        size_t gb = (size_t)(n0 + row) * GK + k0 + c * 8;
        CPA16(sb + o,             Ahi + ga);
        CPA16(sb + TILEB + o,     Alo + ga);
        CPA16(sb + 2 * TILEB + o, Whi + gb);
        CPA16(sb + 3 * TILEB + o, Wlo + gb);
    }
}

__global__ __launch_bounds__(256)
void gemm_hmma_kernel(const __half* __restrict__ Ahi, const __half* __restrict__ Alo,
                      const __half* __restrict__ Whi, const __half* __restrict__ Wlo,
                      const float* __restrict__ bias, float* __restrict__ C, int Nn)
{
    extern __shared__ char dsm[];
    const int tid = threadIdx.x;
    const int lane = tid & 31;
    const int wid = tid >> 5;
    const int wm = (wid & 3) * 32;      // warp m offset (4 warps along M)
    const int wn = (wid >> 2) * 64;     // warp n offset (2 warps along N)
    const int m0 = blockIdx.y * 128;
    const int n0 = blockIdx.x * 128;
    const uint32_t sb = smem_u32(dsm);

    float acc[2][8][4];
#pragma unroll
    for (int mt = 0; mt < 2; mt++)
#pragma unroll
        for (int nt = 0; nt < 8; nt++)
#pragma unroll
            for (int e = 0; e < 4; e++) acc[mt][nt][e] = 0.f;

    // A frag address params: row = l&15, kc offset = l>>4
    const int a_row = lane & 15;
    const int a_kc  = lane >> 4;
    // B frag: n = (l&7) + ((l>>4)<<3), kc = (l>>3)&1
    const int b_row = (lane & 7) + ((lane >> 4) << 3);
    const int b_kc  = (lane >> 3) & 1;

    load_stage(sb, Ahi, Alo, Whi, Wlo, m0, n0, 0, tid);
    CPA_COMMIT();

    for (int k = 0; k < NCHUNK; k++) {
        if (k + 1 < NCHUNK) {
            load_stage(sb + ((k + 1) & 1) * STAGEB, Ahi, Alo, Whi, Wlo,
                       m0, n0, (k + 1) * 32, tid);
            CPA_COMMIT();
            CPA_WAIT(1);
        } else {
            CPA_WAIT(0);
        }
        __syncthreads();

        const uint32_t cs  = sb + (k & 1) * STAGEB;
        const uint32_t sAh = cs, sAl = cs + TILEB, sBh = cs + 2 * TILEB, sBl = cs + 3 * TILEB;

#pragma unroll
        for (int kk = 0; kk < 2; kk++) {            // two k16 steps in BK=32
            const int kc = kk * 2;
            uint32_t ah[2][4], al[2][4];
#pragma unroll
            for (int mt = 0; mt < 2; mt++) {
                uint32_t o = sw_off(wm + mt * 16 + a_row, kc + a_kc);
                LDSM_X4(ah[mt][0], ah[mt][1], ah[mt][2], ah[mt][3], sAh + o);
                LDSM_X4(al[mt][0], al[mt][1], al[mt][2], al[mt][3], sAl + o);
            }
#pragma unroll
            for (int ng = 0; ng < 4; ng++) {        // 4 n16 groups = 64 cols
                uint32_t bh[4], bl[4];
                uint32_t o = sw_off(wn + ng * 16 + b_row, kc + b_kc);
                LDSM_X4(bh[0], bh[1], bh[2], bh[3], sBh + o);
                LDSM_X4(bl[0], bl[1], bl[2], bl[3], sBl + o);
#pragma unroll
                for (int mt = 0; mt < 2; mt++) {
                    MMA16816(acc[mt][ng * 2 + 0], ah[mt], bh[0], bh[1]);
                    MMA16816(acc[mt][ng * 2 + 0], ah[mt], bl[0], bl[1]);
                    MMA16816(acc[mt][ng * 2 + 0], al[mt], bh[0], bh[1]);
                    MMA16816(acc[mt][ng * 2 + 1], ah[mt], bh[2], bh[3]);
                    MMA16816(acc[mt][ng * 2 + 1], ah[mt], bl[2], bl[3]);
                    MMA16816(acc[mt][ng * 2 + 1], al[mt], bh[2], bh[3]);
                }
            }
        }
        __syncthreads();
    }

    // epilogue: c0,c1 -> (row, col..col+1); c2,c3 -> (row+8, col..col+1)
    const int erow = lane >> 2;
    const int ecol = (lane & 3) * 2;
#pragma unroll
    for (int mt = 0; mt < 2; mt++) {
#pragma unroll
        for (int nt = 0; nt < 8; nt++) {
            int col = n0 + wn + nt * 8 + ecol;
            float b0 = __ldg(bias + col), b1 = __ldg(bias + col + 1);
            int r0 = m0 + wm + mt * 16 + erow;
            float2 v0 = make_float2(acc[mt][nt][0] + b0, acc[mt][nt][1] + b1);
            float2 v1 = make_float2(acc[mt][nt][2] + b0, acc[mt][nt][3] + b1);
            *(float2*)(C + (size_t)r0 * Nn + col)       = v0;
            *(float2*)(C + (size_t)(r0 + 8) * Nn + col) = v1;
        }
    }
}

// ---------------- fused attention (fp32; epilogue emits fp16 hi/lo) ----------------
__global__ __launch_bounds__(256) void attn_kernel(
    const float* __restrict__ qkv, const float* __restrict__ bias,
    __half* __restrict__ aohi, __half* __restrict__ aolo)
{
    extern __shared__ float sm[];
    float* Vs  = sm + OFF_VS;
    float* Ks  = sm + OFF_KS;
    float* Qs  = sm + OFF_QS;
    float* Sc  = sm + OFF_SC;
    float* Inv = sm + OFF_INV;

    const int b = blockIdx.x / HH;
    const int h = blockIdx.x % HH;
    const int tid = threadIdx.x;
    const float scale = 0.125f;
    const float* base = qkv + (size_t)b * NT * 2304 + h * 64;

    for (int p = tid; p < NT * 16; p += 256) {
        int n = p >> 4, f = (p & 15) << 2;
        float4 kv = *(const float4*)(base + (size_t)n * 2304 + 768 + f);
        Ks[n * KS_STRIDE + f + 0] = kv.x; Ks[n * KS_STRIDE + f + 1] = kv.y;
        Ks[n * KS_STRIDE + f + 2] = kv.z; Ks[n * KS_STRIDE + f + 3] = kv.w;
        float4 vv = *(const float4*)(base + (size_t)n * 2304 + 1536 + f);
        *(float4*)(Vs + n * HD + f) = vv;
    }
    const float* biasH = bias + (size_t)h * NT * NT;
    const int ty = tid >> 5, tx = tid & 31;
    __syncthreads();

    for (int qt = 0; qt < 7; qt++) {
        const int r0 = qt * 32;
        const int rows = min(32, NT - r0);

        for (int p = tid; p < 32 * 16; p += 256) {
            int n = p >> 4, f = (p & 15) << 2;
            if (n < rows) {
                float4 qv = *(const float4*)(base + (size_t)(r0 + n) * 2304 + f);
                Qs[n * HD + f + 0] = qv.x * scale; Qs[n * HD + f + 1] = qv.y * scale;
                Qs[n * HD + f + 2] = qv.z * scale; Qs[n * HD + f + 3] = qv.w * scale;
            } else {
                Qs[n * HD + f + 0] = 0.f; Qs[n * HD + f + 1] = 0.f;
                Qs[n * HD + f + 2] = 0.f; Qs[n * HD + f + 3] = 0.f;
            }
        }
        __syncthreads();

        {
            int cc[7]; bool cv[7];
#pragma unroll
            for (int ci = 0; ci < 7; ci++) {
                int c = tx + 32 * ci; cv[ci] = (c < NT); cc[ci] = cv[ci] ? c : (NT - 1);
            }
            float acc[4][7];
#pragma unroll
            for (int i = 0; i < 4; i++) {
                int r = ty * 4 + i;
#pragma unroll
                for (int ci = 0; ci < 7; ci++)
                    acc[i][ci] = (r < rows && cv[ci])
                               ? biasH[(size_t)(r0 + r) * NT + cc[ci]] : 0.f;
            }
#pragma unroll 4
            for (int d = 0; d < HD; d++) {
                float q0 = Qs[(ty * 4 + 0) * HD + d];
                float q1 = Qs[(ty * 4 + 1) * HD + d];
                float q2 = Qs[(ty * 4 + 2) * HD + d];
                float q3 = Qs[(ty * 4 + 3) * HD + d];
#pragma unroll
                for (int ci = 0; ci < 7; ci++) {
                    float kv = Ks[cc[ci] * KS_STRIDE + d];
                    acc[0][ci] += q0 * kv;
                    acc[1][ci] += q1 * kv;
                    acc[2][ci] += q2 * kv;
                    acc[3][ci] += q3 * kv;
                }
            }
#pragma unroll
            for (int i = 0; i < 4; i++) {
                int r = ty * 4 + i;
                if (r < rows) {
#pragma unroll
                    for (int ci = 0; ci < 7; ci++)
                        if (cv[ci]) Sc[r * SC_STRIDE + cc[ci]] = acc[i][ci];
                }
            }
        }
        __syncthreads();

#pragma unroll
        for (int i = 0; i < 4; i++) {
            int r = ty * 4 + i;
            if (r < rows) {
                float m = -3.4e38f;
                for (int c = tx; c < NT; c += 32) m = fmaxf(m, Sc[r * SC_STRIDE + c]);
#pragma unroll
                for (int o = 16; o > 0; o >>= 1) m = fmaxf(m, __shfl_xor_sync(0xffffffffu, m, o));
                float s = 0.f;
                for (int c = tx; c < NT; c += 32) {
                    float e = __expf(Sc[r * SC_STRIDE + c] - m);
                    Sc[r * SC_STRIDE + c] = e;
                    s += e;
                }
#pragma unroll
                for (int o = 16; o > 0; o >>= 1) s += __shfl_xor_sync(0xffffffffu, s, o);
                if (tx == 0) Inv[r] = 1.f / s;
            }
        }
        __syncthreads();

        {
            float o[4][2] = {};
            for (int c = 0; c < NT; c++) {
                float v0 = Vs[c * HD + tx];
                float v1 = Vs[c * HD + tx + 32];
#pragma unroll
                for (int i = 0; i < 4; i++) {
                    float s = Sc[(ty * 4 + i) * SC_STRIDE + c];
                    o[i][0] += s * v0;
                    o[i][1] += s * v1;
                }
            }
#pragma unroll
            for (int i = 0; i < 4; i++) {
                int r = ty * 4 + i;
                if (r < rows) {
                    float inv = Inv[r];
                    size_t off = ((size_t)b * NT + r0 + r) * DIM_ + h * 64;
                    __half h0, l0, h1, l1;
                    h_split(o[i][0] * inv, h0, l0);
                    h_split(o[i][1] * inv, h1, l1);
                    aohi[off + tx]      = h0; aolo[off + tx]      = l0;
                    aohi[off + tx + 32] = h1; aolo[off + tx + 32] = l1;
                }
            }
        }
        __syncthreads();
    }
}

// ---------------- launch ----------------
extern "C" void kernel_launch(void* const* d_in, const int* in_sizes, int n_in,
                              void* d_out, int out_size)
{
    const float* x      = (const float*)d_in[0];
    const float* qkv_w  = (const float*)d_in[1];
    const float* qkv_b  = (const float*)d_in[2];
    const float* proj_w = (const float*)d_in[3];
    const float* proj_b = (const float*)d_in[4];
    const float* table  = (const float*)d_in[5];
    const int*   relidx = (const int*)d_in[6];
    float* out = (float*)d_out;

    float *p_qkv, *p_bias;
    __half *p_xhi, *p_xlo, *p_aohi, *p_aolo, *p_qwhi, *p_qwlo, *p_pwhi, *p_pwlo;
    cudaGetSymbolAddress((void**)&p_qkv,  g_qkv);
    cudaGetSymbolAddress((void**)&p_xhi,  g_xhi);
    cudaGetSymbolAddress((void**)&p_xlo,  g_xlo);
    cudaGetSymbolAddress((void**)&p_aohi, g_aohi);
    cudaGetSymbolAddress((void**)&p_aolo, g_aolo);
    cudaGetSymbolAddress((void**)&p_qwhi, g_qwhi);
    cudaGetSymbolAddress((void**)&p_qwlo, g_qwlo);
    cudaGetSymbolAddress((void**)&p_pwhi, g_pwhi);
    cudaGetSymbolAddress((void**)&p_pwlo, g_pwlo);
    cudaGetSymbolAddress((void**)&p_bias, g_bias);

    const int smem_att = SMEM_FLOATS * 4;
    cudaFuncSetAttribute(attn_kernel, cudaFuncAttributeMaxDynamicSharedMemorySize, smem_att);
    cudaFuncSetAttribute(gemm_hmma_kernel, cudaFuncAttributeMaxDynamicSharedMemorySize, GSMEM);

    const int nx = MTOK * DIM_;
    split_kernel<<<(nx + 255) / 256, 256>>>(x, p_xhi, p_xlo, nx);
    split_kernel<<<(2304 * DIM_ + 255) / 256, 256>>>(qkv_w, p_qwhi, p_qwlo, 2304 * DIM_);
    split_kernel<<<(DIM_ * DIM_ + 255) / 256, 256>>>(proj_w, p_pwhi, p_pwlo, DIM_ * DIM_);

    bias_kernel<<<(HH * NT * NT + 255) / 256, 256>>>(table, relidx, p_bias);

    dim3 g1(2304 / 128, MTOK / 128);
    gemm_hmma_kernel<<<g1, 256, GSMEM>>>(p_xhi, p_xlo, p_qwhi, p_qwlo, qkv_b, p_qkv, 2304);

    attn_kernel<<<B_ * HH, 256, smem_att>>>(p_qkv, p_bias, p_aohi, p_aolo);

    dim3 g2(DIM_ / 128, MTOK / 128);
    gemm_hmma_kernel<<<g2, 256, GSMEM>>>(p_aohi, p_aolo, p_pwhi, p_pwlo, proj_b, out, DIM_);
}

// round 5
// speedup vs baseline: 1.9354x; 1.1333x over previous
#include <cuda_runtime.h>
#include <cuda_fp16.h>
#include <cstdint>

#define B_   128
#define NT   197
#define HH   12
#define HD   64
#define DIM_ 768
#define MTOK (B_ * NT)          // 25216 = 197*128

// ---------------- scratch ----------------
__device__ float  g_qkv [(long long)MTOK * 2304];
__device__ __half g_xhi [(long long)MTOK * DIM_];
__device__ __half g_xlo [(long long)MTOK * DIM_];
__device__ __half g_aohi[(long long)MTOK * DIM_];
__device__ __half g_aolo[(long long)MTOK * DIM_];
__device__ __half g_qwhi[2304 * DIM_];
__device__ __half g_qwlo[2304 * DIM_];
__device__ __half g_pwhi[DIM_ * DIM_];
__device__ __half g_pwlo[DIM_ * DIM_];
__device__ float  g_bias[HH * NT * NT];

// ---------------- helpers ----------------
__device__ __forceinline__ uint32_t smem_u32(const void* p) {
    uint32_t a;
    asm("{ .reg .u64 t; cvta.to.shared.u64 t, %1; cvt.u32.u64 %0, t; }" : "=r"(a) : "l"(p));
    return a;
}

#define CPA16(dst, src)   asm volatile("cp.async.cg.shared.global [%0], [%1], 16;" :: "r"(dst), "l"(src) : "memory")
#define CPA_COMMIT()      asm volatile("cp.async.commit_group;" ::: "memory")
#define CPA_WAIT(n)       asm volatile("cp.async.wait_group %0;" :: "n"(n) : "memory")

#define LDSM_X4(r0, r1, r2, r3, addr) \
    asm volatile("ldmatrix.sync.aligned.m8n8.x4.shared.b16 {%0,%1,%2,%3}, [%4];" \
        : "=r"(r0), "=r"(r1), "=r"(r2), "=r"(r3) : "r"(addr))

#define MMA16816(d, a, b0, b1) \
    asm volatile("mma.sync.aligned.m16n8k16.row.col.f32.f16.f16.f32 " \
        "{%0,%1,%2,%3}, {%4,%5,%6,%7}, {%8,%9}, {%0,%1,%2,%3};" \
        : "+f"((d)[0]), "+f"((d)[1]), "+f"((d)[2]), "+f"((d)[3]) \
        : "r"((a)[0]), "r"((a)[1]), "r"((a)[2]), "r"((a)[3]), "r"(b0), "r"(b1))

// swizzled tile offset for 64B rows (gemm tiles): chunk 0..3
__device__ __forceinline__ uint32_t sw_off(int row, int chunk) {
    return (uint32_t)(row * 64 + ((chunk ^ ((row >> 1) & 3)) << 4));
}
// swizzled offset for 128B rows (attention K/Q tiles): chunk 0..7
__device__ __forceinline__ uint32_t swb(int row, int chunk) {
    return (uint32_t)(row * 128 + ((chunk ^ (row & 7)) << 4));
}

static __device__ __forceinline__ void h_split(float v, __half& hi, __half& lo) {
    hi = __float2half_rn(v);
    lo = __float2half_rn(v - __half2float(hi));
}

// ---------------- elementwise fp16 split ----------------
__global__ void split_kernel(const float* __restrict__ in,
                             __half* __restrict__ hi, __half* __restrict__ lo, int n)
{
    int t = blockIdx.x * 256 + threadIdx.x;
    if (t < n) {
        __half h, l;
        h_split(in[t], h, l);
        hi[t] = h; lo[t] = l;
    }
}

// ---------------- bias gather ----------------
__global__ void bias_kernel(const float* __restrict__ table,
                            const int*   __restrict__ idx,
                            float* __restrict__ out)
{
    int t = blockIdx.x * blockDim.x + threadIdx.x;
    if (t < HH * NT * NT) {
        int ij = t % (NT * NT);
        int h  = t / (NT * NT);
        out[t] = table[idx[ij] * HH + h];
    }
}

// ---------------- 3xFP16 mma.sync GEMM (unchanged from R4) ----------------
#define GK     768
#define NCHUNK 24
#define TILEB  8192
#define STAGEB (4 * TILEB)
#define GSMEM  (2 * STAGEB)

static __device__ __forceinline__ void load_stage(
    uint32_t sb, const __half* __restrict__ Ahi, const __half* __restrict__ Alo,
    const __half* __restrict__ Whi, const __half* __restrict__ Wlo,
    int m0, int n0, int k0, int tid)
{
#pragma unroll
    for (int j = 0; j < 2; j++) {
        int id = tid + (j << 8);
        int row = id >> 2, c = id & 3;
        uint32_t o = sw_off(row, c);
        size_t ga = (size_t)(m0 + row) * GK + k0 + c * 8;
        size_t gb = (size_t)(n0 + row) * GK + k0 + c * 8;
        CPA16(sb + o,             Ahi + ga);
        CPA16(sb + TILEB + o,     Alo + ga);
        CPA16(sb + 2 * TILEB + o, Whi + gb);
        CPA16(sb + 3 * TILEB + o, Wlo + gb);
    }
}

__global__ __launch_bounds__(256)
void gemm_hmma_kernel(const __half* __restrict__ Ahi, const __half* __restrict__ Alo,
                      const __half* __restrict__ Whi, const __half* __restrict__ Wlo,
                      const float* __restrict__ bias, float* __restrict__ C, int Nn)
{
    extern __shared__ char dsm[];
    const int tid = threadIdx.x;
    const int lane = tid & 31;
    const int wid = tid >> 5;
    const int wm = (wid & 3) * 32;
    const int wn = (wid >> 2) * 64;
    const int m0 = blockIdx.y * 128;
    const int n0 = blockIdx.x * 128;
    const uint32_t sb = smem_u32(dsm);

    float acc[2][8][4];
#pragma unroll
    for (int mt = 0; mt < 2; mt++)
#pragma unroll
        for (int nt = 0; nt < 8; nt++)
#pragma unroll
            for (int e = 0; e < 4; e++) acc[mt][nt][e] = 0.f;

    const int a_row = lane & 15;
    const int a_kc  = lane >> 4;
    const int b_row = (lane & 7) + ((lane >> 4) << 3);
    const int b_kc  = (lane >> 3) & 1;

    load_stage(sb, Ahi, Alo, Whi, Wlo, m0, n0, 0, tid);
    CPA_COMMIT();

    for (int k = 0; k < NCHUNK; k++) {
        if (k + 1 < NCHUNK) {
            load_stage(sb + ((k + 1) & 1) * STAGEB, Ahi, Alo, Whi, Wlo,
                       m0, n0, (k + 1) * 32, tid);
            CPA_COMMIT();
            CPA_WAIT(1);
        } else {
            CPA_WAIT(0);
        }
        __syncthreads();

        const uint32_t cs  = sb + (k & 1) * STAGEB;
        const uint32_t sAh = cs, sAl = cs + TILEB, sBh = cs + 2 * TILEB, sBl = cs + 3 * TILEB;

#pragma unroll
        for (int kk = 0; kk < 2; kk++) {
            const int kc = kk * 2;
            uint32_t ah[2][4], al[2][4];
#pragma unroll
            for (int mt = 0; mt < 2; mt++) {
                uint32_t o = sw_off(wm + mt * 16 + a_row, kc + a_kc);
                LDSM_X4(ah[mt][0], ah[mt][1], ah[mt][2], ah[mt][3], sAh + o);
                LDSM_X4(al[mt][0], al[mt][1], al[mt][2], al[mt][3], sAl + o);
            }
#pragma unroll
            for (int ng = 0; ng < 4; ng++) {
                uint32_t bh[4], bl[4];
                uint32_t o = sw_off(wn + ng * 16 + b_row, kc + b_kc);
                LDSM_X4(bh[0], bh[1], bh[2], bh[3], sBh + o);
                LDSM_X4(bl[0], bl[1], bl[2], bl[3], sBl + o);
#pragma unroll
                for (int mt = 0; mt < 2; mt++) {
                    MMA16816(acc[mt][ng * 2 + 0], ah[mt], bh[0], bh[1]);
                    MMA16816(acc[mt][ng * 2 + 0], ah[mt], bl[0], bl[1]);
                    MMA16816(acc[mt][ng * 2 + 0], al[mt], bh[0], bh[1]);
                    MMA16816(acc[mt][ng * 2 + 1], ah[mt], bh[2], bh[3]);
                    MMA16816(acc[mt][ng * 2 + 1], ah[mt], bl[2], bl[3]);
                    MMA16816(acc[mt][ng * 2 + 1], al[mt], bh[2], bh[3]);
                }
            }
        }
        __syncthreads();
    }

    const int erow = lane >> 2;
    const int ecol = (lane & 3) * 2;
#pragma unroll
    for (int mt = 0; mt < 2; mt++) {
#pragma unroll
        for (int nt = 0; nt < 8; nt++) {
            int col = n0 + wn + nt * 8 + ecol;
            float b0 = __ldg(bias + col), b1 = __ldg(bias + col + 1);
            int r0 = m0 + wm + mt * 16 + erow;
            float2 v0 = make_float2(acc[mt][nt][0] + b0, acc[mt][nt][1] + b1);
            float2 v1 = make_float2(acc[mt][nt][2] + b0, acc[mt][nt][3] + b1);
            *(float2*)(C + (size_t)r0 * Nn + col)       = v0;
            *(float2*)(C + (size_t)(r0 + 8) * Nn + col) = v1;
        }
    }
}

// ---------------- HMMA attention ----------------
// SMEM byte offsets
#define KP     256                    // padded keys for S phase
#define PSTRH  232                    // P / Vt row pitch in halves (464 B)
#define SSTR   258                    // S row pitch in floats
#define A_KH   0
#define A_KL   (A_KH + KP * 128)                 // 32768
#define A_QH   (A_KL + KP * 128)                 // 65536
#define A_QL   (A_QH + 32 * 128)                 // 69632
#define A_VTH  (A_QL + 32 * 128)                 // 73728
#define A_VTL  (A_VTH + 64 * PSTRH * 2)          // 103424
#define A_S    (A_VTL + 64 * PSTRH * 2)          // 133120
#define A_PH   (A_S + 32 * SSTR * 4)             // 166144
#define A_PL   (A_PH + 32 * PSTRH * 2)           // 180992
#define A_INV  (A_PL + 32 * PSTRH * 2)           // 195840
#define A_TOT  (A_INV + 128)                     // 195968

__global__ __launch_bounds__(256) void attn_hmma_kernel(
    const float* __restrict__ qkv, const float* __restrict__ bias,
    __half* __restrict__ aohi, __half* __restrict__ aolo)
{
    extern __shared__ char smb[];
    const uint32_t sb = smem_u32(smb);
    const int b = blockIdx.x / HH;
    const int h = blockIdx.x % HH;
    const int tid = threadIdx.x, lane = tid & 31, wid = tid >> 5;
    const float* base = qkv + (size_t)b * NT * 2304 + h * 64;
    const float* biasH = bias + (size_t)h * NT * NT;

    // zero Vt (h+l contiguous), P (h+l contiguous), K pad rows
    for (int i = tid; i < (64 * PSTRH * 2 * 2) / 4; i += 256)
        ((uint32_t*)(smb + A_VTH))[i] = 0;
    for (int i = tid; i < (32 * PSTRH * 2 * 2) / 4; i += 256)
        ((uint32_t*)(smb + A_PH))[i] = 0;
    for (int i = tid; i < ((KP - NT) * 128) / 4; i += 256) {
        ((uint32_t*)(smb + A_KH + NT * 128))[i] = 0;
        ((uint32_t*)(smb + A_KL + NT * 128))[i] = 0;
    }
    __syncthreads();

    // load K (SW128 rows) + V transposed (Vt[d][key])
    for (int p = tid; p < NT * 64; p += 256) {
        int key = p >> 6, d = p & 63;
        __half kh, kl, vh, vl;
        h_split(base[(size_t)key * 2304 + 768 + d], kh, kl);
        h_split(base[(size_t)key * 2304 + 1536 + d], vh, vl);
        uint32_t ko = (uint32_t)(key * 128) + ((((d >> 3) ^ (key & 7))) << 4) + ((d & 7) << 1);
        *(__half*)(smb + A_KH + ko) = kh;
        *(__half*)(smb + A_KL + ko) = kl;
        uint32_t vo = (uint32_t)(d * (PSTRH * 2) + key * 2);
        *(__half*)(smb + A_VTH + vo) = vh;
        *(__half*)(smb + A_VTL + vo) = vl;
    }
    __syncthreads();

    const int a_row16 = lane & 15;
    const int b_row8  = (lane & 7) + ((lane >> 4) << 3);
    const int b_kc1   = (lane >> 3) & 1;

    for (int qt = 0; qt < 7; qt++) {
        const int r0 = qt * 32;
        const int rows = min(32, NT - r0);

        // load Q (pre-scaled, SW128 rows, zero-padded rows)
        for (int p = tid; p < 32 * 64; p += 256) {
            int r = p >> 6, d = p & 63;
            float qv = (r < rows) ? base[(size_t)(r0 + r) * 2304 + d] * 0.125f : 0.f;
            __half qh, ql;
            h_split(qv, qh, ql);
            uint32_t qo = (uint32_t)(r * 128) + ((((d >> 3) ^ (r & 7))) << 4) + ((d & 7) << 1);
            *(__half*)(smb + A_QH + qo) = qh;
            *(__half*)(smb + A_QL + qo) = ql;
        }
        __syncthreads();

        // ---- S = Q K^T (+bias), 3-term split HMMA ----
        {
            const int wm = (wid & 1) * 16;
            const int wn = (wid >> 1) * 64;
            float acc[8][4];
#pragma unroll
            for (int t = 0; t < 8; t++)
#pragma unroll
                for (int e = 0; e < 4; e++) acc[t][e] = 0.f;

            const int ar = wm + a_row16;
#pragma unroll
            for (int kk = 0; kk < 4; kk++) {
                const int ac = kk * 2 + (lane >> 4);
                uint32_t aoff = swb(ar, ac);
                uint32_t ah[4], al[4];
                LDSM_X4(ah[0], ah[1], ah[2], ah[3], sb + A_QH + aoff);
                LDSM_X4(al[0], al[1], al[2], al[3], sb + A_QL + aoff);
#pragma unroll
                for (int ng = 0; ng < 4; ng++) {
                    const int br = wn + ng * 16 + b_row8;
                    uint32_t boff = swb(br, kk * 2 + b_kc1);
                    uint32_t bh[4], bl[4];
                    LDSM_X4(bh[0], bh[1], bh[2], bh[3], sb + A_KH + boff);
                    LDSM_X4(bl[0], bl[1], bl[2], bl[3], sb + A_KL + boff);
                    MMA16816(acc[ng * 2 + 0], ah, bh[0], bh[1]);
                    MMA16816(acc[ng * 2 + 0], ah, bl[0], bl[1]);
                    MMA16816(acc[ng * 2 + 0], al, bh[0], bh[1]);
                    MMA16816(acc[ng * 2 + 1], ah, bh[2], bh[3]);
                    MMA16816(acc[ng * 2 + 1], ah, bl[2], bl[3]);
                    MMA16816(acc[ng * 2 + 1], al, bh[2], bh[3]);
                }
            }
            // epilogue: add bias, store to S
            const int erow = wm + (lane >> 2);
            const int ecol = (lane & 3) * 2;
            float* S = (float*)(smb + A_S);
#pragma unroll
            for (int nt = 0; nt < 8; nt++) {
                int col = wn + nt * 8 + ecol;
                float b00 = 0.f, b01 = 0.f, b10 = 0.f, b11 = 0.f;
                if (col < NT) {
                    int gr0 = r0 + erow, gr1 = r0 + erow + 8;
                    bool c1 = (col + 1 < NT);
                    if (gr0 < NT) {
                        b00 = biasH[(size_t)gr0 * NT + col];
                        if (c1) b01 = biasH[(size_t)gr0 * NT + col + 1];
                    }
                    if (gr1 < NT) {
                        b10 = biasH[(size_t)gr1 * NT + col];
                        if (c1) b11 = biasH[(size_t)gr1 * NT + col + 1];
                    }
                }
                *(float2*)(S + erow * SSTR + col)       = make_float2(acc[nt][0] + b00, acc[nt][1] + b01);
                *(float2*)(S + (erow + 8) * SSTR + col) = make_float2(acc[nt][2] + b10, acc[nt][3] + b11);
            }
        }
        __syncthreads();

        // ---- softmax (fp32), emit P hi/lo fp16 ----
        {
            float* S = (float*)(smb + A_S);
            __half* PH = (__half*)(smb + A_PH);
            __half* PL = (__half*)(smb + A_PL);
            float* INV = (float*)(smb + A_INV);
#pragma unroll
            for (int i = 0; i < 4; i++) {
                int r = wid * 4 + i;
                if (r < rows) {
                    float m = -3.4e38f;
                    for (int c = lane; c < NT; c += 32) m = fmaxf(m, S[r * SSTR + c]);
#pragma unroll
                    for (int o = 16; o > 0; o >>= 1) m = fmaxf(m, __shfl_xor_sync(0xffffffffu, m, o));
                    float s = 0.f;
                    for (int c = lane; c < NT; c += 32) {
                        float e = __expf(S[r * SSTR + c] - m);
                        s += e;
                        __half eh, el;
                        h_split(e, eh, el);
                        PH[r * PSTRH + c] = eh;
                        PL[r * PSTRH + c] = el;
                    }
#pragma unroll
                    for (int o = 16; o > 0; o >>= 1) s += __shfl_xor_sync(0xffffffffu, s, o);
                    if (lane == 0) INV[r] = 1.f / s;
                }
            }
        }
        __syncthreads();

        // ---- AV = P V, 3-term split HMMA (k = 208 keys padded) ----
        {
            const int wm = (wid & 1) * 16;
            const int wd = (wid >> 1) * 16;
            float acc[2][4];
#pragma unroll
            for (int t = 0; t < 2; t++)
#pragma unroll
                for (int e = 0; e < 4; e++) acc[t][e] = 0.f;

            const int ar = wm + a_row16;
            const int br = wd + b_row8;
#pragma unroll
            for (int kk = 0; kk < 13; kk++) {
                uint32_t aoff = (uint32_t)(ar * (PSTRH * 2) + (kk * 2 + (lane >> 4)) * 16);
                uint32_t ah[4], al[4];
                LDSM_X4(ah[0], ah[1], ah[2], ah[3], sb + A_PH + aoff);
                LDSM_X4(al[0], al[1], al[2], al[3], sb + A_PL + aoff);
                uint32_t boff = (uint32_t)(br * (PSTRH * 2) + (kk * 2 + b_kc1) * 16);
                uint32_t bh[4], bl[4];
                LDSM_X4(bh[0], bh[1], bh[2], bh[3], sb + A_VTH + boff);
                LDSM_X4(bl[0], bl[1], bl[2], bl[3], sb + A_VTL + boff);
                MMA16816(acc[0], ah, bh[0], bh[1]);
                MMA16816(acc[0], ah, bl[0], bl[1]);
                MMA16816(acc[0], al, bh[0], bh[1]);
                MMA16816(acc[1], ah, bh[2], bh[3]);
                MMA16816(acc[1], ah, bl[2], bl[3]);
                MMA16816(acc[1], al, bh[2], bh[3]);
            }
            // epilogue: normalize, split, store to global hi/lo
            const int erow = wm + (lane >> 2);
            const int ec = (lane & 3) * 2;
            float* INV = (float*)(smb + A_INV);
#pragma unroll
            for (int hf = 0; hf < 2; hf++) {
                int rr = erow + hf * 8;
                if (rr < rows) {
                    float inv = INV[rr];
                    size_t gb = ((size_t)b * NT + r0 + rr) * DIM_ + h * 64 + wd;
#pragma unroll
                    for (int nt = 0; nt < 2; nt++) {
                        int d = nt * 8 + ec;
                        __half h0, l0, h1, l1;
                        h_split(acc[nt][hf * 2 + 0] * inv, h0, l0);
                        h_split(acc[nt][hf * 2 + 1] * inv, h1, l1);
                        aohi[gb + d]     = h0; aolo[gb + d]     = l0;
                        aohi[gb + d + 1] = h1; aolo[gb + d + 1] = l1;
                    }
                }
            }
        }
        __syncthreads();
    }
}

// ---------------- launch ----------------
extern "C" void kernel_launch(void* const* d_in, const int* in_sizes, int n_in,
                              void* d_out, int out_size)
{
    const float* x      = (const float*)d_in[0];
    const float* qkv_w  = (const float*)d_in[1];
    const float* qkv_b  = (const float*)d_in[2];
    const float* proj_w = (const float*)d_in[3];
    const float* proj_b = (const float*)d_in[4];
    const float* table  = (const float*)d_in[5];
    const int*   relidx = (const int*)d_in[6];
    float* out = (float*)d_out;

    float *p_qkv, *p_bias;
    __half *p_xhi, *p_xlo, *p_aohi, *p_aolo, *p_qwhi, *p_qwlo, *p_pwhi, *p_pwlo;
    cudaGetSymbolAddress((void**)&p_qkv,  g_qkv);
    cudaGetSymbolAddress((void**)&p_xhi,  g_xhi);
    cudaGetSymbolAddress((void**)&p_xlo,  g_xlo);
    cudaGetSymbolAddress((void**)&p_aohi, g_aohi);
    cudaGetSymbolAddress((void**)&p_aolo, g_aolo);
    cudaGetSymbolAddress((void**)&p_qwhi, g_qwhi);
    cudaGetSymbolAddress((void**)&p_qwlo, g_qwlo);
    cudaGetSymbolAddress((void**)&p_pwhi, g_pwhi);
    cudaGetSymbolAddress((void**)&p_pwlo, g_pwlo);
    cudaGetSymbolAddress((void**)&p_bias, g_bias);

    cudaFuncSetAttribute(attn_hmma_kernel, cudaFuncAttributeMaxDynamicSharedMemorySize, A_TOT);
    cudaFuncSetAttribute(gemm_hmma_kernel, cudaFuncAttributeMaxDynamicSharedMemorySize, GSMEM);

    const int nx = MTOK * DIM_;
    split_kernel<<<(nx + 255) / 256, 256>>>(x, p_xhi, p_xlo, nx);
    split_kernel<<<(2304 * DIM_ + 255) / 256, 256>>>(qkv_w, p_qwhi, p_qwlo, 2304 * DIM_);
    split_kernel<<<(DIM_ * DIM_ + 255) / 256, 256>>>(proj_w, p_pwhi, p_pwlo, DIM_ * DIM_);

    bias_kernel<<<(HH * NT * NT + 255) / 256, 256>>>(table, relidx, p_bias);

    dim3 g1(2304 / 128, MTOK / 128);
    gemm_hmma_kernel<<<g1, 256, GSMEM>>>(p_xhi, p_xlo, p_qwhi, p_qwlo, qkv_b, p_qkv, 2304);

    attn_hmma_kernel<<<B_ * HH, 256, A_TOT>>>(p_qkv, p_bias, p_aohi, p_aolo);

    dim3 g2(DIM_ / 128, MTOK / 128);
    gemm_hmma_kernel<<<g2, 256, GSMEM>>>(p_aohi, p_aolo, p_pwhi, p_pwlo, proj_b, out, DIM_);
}

// round 6
// speedup vs baseline: 2.3293x; 1.2035x over previous
#include <cuda_runtime.h>
#include <cuda_fp16.h>
#include <cstdint>

#define B_   128
#define NT   197
#define HH   12
#define HD   64
#define DIM_ 768
#define MTOK (B_ * NT)          // 25216 = 197*128

// ---------------- scratch ----------------
__device__ __half g_qhi [(long long)MTOK * 2304];   // qkv output hi
__device__ __half g_qlo [(long long)MTOK * 2304];   // qkv output lo
__device__ __half g_xhi [(long long)MTOK * DIM_];
__device__ __half g_xlo [(long long)MTOK * DIM_];
__device__ __half g_aohi[(long long)MTOK * DIM_];
__device__ __half g_aolo[(long long)MTOK * DIM_];
__device__ __half g_qwhi[2304 * DIM_];
__device__ __half g_qwlo[2304 * DIM_];
__device__ __half g_pwhi[DIM_ * DIM_];
__device__ __half g_pwlo[DIM_ * DIM_];
__device__ float  g_bias[HH * NT * NT];

// ---------------- helpers ----------------
__device__ __forceinline__ uint32_t smem_u32(const void* p) {
    uint32_t a;
    asm("{ .reg .u64 t; cvta.to.shared.u64 t, %1; cvt.u32.u64 %0, t; }" : "=r"(a) : "l"(p));
    return a;
}

#define CPA16(dst, src)   asm volatile("cp.async.cg.shared.global [%0], [%1], 16;" :: "r"(dst), "l"(src) : "memory")
#define CPA_COMMIT()      asm volatile("cp.async.commit_group;" ::: "memory")
#define CPA_WAIT(n)       asm volatile("cp.async.wait_group %0;" :: "n"(n) : "memory")

#define LDSM_X4(r0, r1, r2, r3, addr) \
    asm volatile("ldmatrix.sync.aligned.m8n8.x4.shared.b16 {%0,%1,%2,%3}, [%4];" \
        : "=r"(r0), "=r"(r1), "=r"(r2), "=r"(r3) : "r"(addr))

#define LDSM_X4_T(r0, r1, r2, r3, addr) \
    asm volatile("ldmatrix.sync.aligned.m8n8.x4.trans.shared.b16 {%0,%1,%2,%3}, [%4];" \
        : "=r"(r0), "=r"(r1), "=r"(r2), "=r"(r3) : "r"(addr))

#define MMA16816(d, a, b0, b1) \
    asm volatile("mma.sync.aligned.m16n8k16.row.col.f32.f16.f16.f32 " \
        "{%0,%1,%2,%3}, {%4,%5,%6,%7}, {%8,%9}, {%0,%1,%2,%3};" \
        : "+f"((d)[0]), "+f"((d)[1]), "+f"((d)[2]), "+f"((d)[3]) \
        : "r"((a)[0]), "r"((a)[1]), "r"((a)[2]), "r"((a)[3]), "r"(b0), "r"(b1))

// swizzled tile offset for 64B rows (gemm tiles): chunk 0..3
__device__ __forceinline__ uint32_t sw_off(int row, int chunk) {
    return (uint32_t)(row * 64 + ((chunk ^ ((row >> 1) & 3)) << 4));
}
// swizzled offset for 128B rows (attention tiles): chunk 0..7
__device__ __forceinline__ uint32_t swb(int row, int chunk) {
    return (uint32_t)(row * 128 + ((chunk ^ (row & 7)) << 4));
}

static __device__ __forceinline__ void h_split(float v, __half& hi, __half& lo) {
    hi = __float2half_rn(v);
    lo = __float2half_rn(v - __half2float(hi));
}

// ---------------- elementwise fp16 split ----------------
__global__ void split_kernel(const float* __restrict__ in,
                             __half* __restrict__ hi, __half* __restrict__ lo, int n)
{
    int t = blockIdx.x * 256 + threadIdx.x;
    if (t < n) {
        __half h, l;
        h_split(in[t], h, l);
        hi[t] = h; lo[t] = l;
    }
}

// ---------------- bias gather ----------------
__global__ void bias_kernel(const float* __restrict__ table,
                            const int*   __restrict__ idx,
                            float* __restrict__ out)
{
    int t = blockIdx.x * blockDim.x + threadIdx.x;
    if (t < HH * NT * NT) {
        int ij = t % (NT * NT);
        int h  = t / (NT * NT);
        out[t] = table[idx[ij] * HH + h];
    }
}

// ---------------- 3xFP16 mma.sync GEMM ----------------
#define GK     768
#define NCHUNK 24
#define TILEB  8192
#define STAGEB (4 * TILEB)
#define GSMEM  (2 * STAGEB)

static __device__ __forceinline__ void load_stage(
    uint32_t sb, const __half* __restrict__ Ahi, const __half* __restrict__ Alo,
    const __half* __restrict__ Whi, const __half* __restrict__ Wlo,
    int m0, int n0, int k0, int tid)
{
#pragma unroll
    for (int j = 0; j < 2; j++) {
        int id = tid + (j << 8);
        int row = id >> 2, c = id & 3;
        uint32_t o = sw_off(row, c);
        size_t ga = (size_t)(m0 + row) * GK + k0 + c * 8;
        size_t gb = (size_t)(n0 + row) * GK + k0 + c * 8;
        CPA16(sb + o,             Ahi + ga);
        CPA16(sb + TILEB + o,     Alo + ga);
        CPA16(sb + 2 * TILEB + o, Whi + gb);
        CPA16(sb + 3 * TILEB + o, Wlo + gb);
    }
}

template<bool SPLIT>
__global__ __launch_bounds__(256)
void gemm_hmma_kernel(const __half* __restrict__ Ahi, const __half* __restrict__ Alo,
                      const __half* __restrict__ Whi, const __half* __restrict__ Wlo,
                      const float* __restrict__ bias, float* __restrict__ C,
                      __half* __restrict__ Chi, __half* __restrict__ Clo, int Nn)
{
    extern __shared__ char dsm[];
    const int tid = threadIdx.x;
    const int lane = tid & 31;
    const int wid = tid >> 5;
    const int wm = (wid & 3) * 32;
    const int wn = (wid >> 2) * 64;
    const int m0 = blockIdx.y * 128;
    const int n0 = blockIdx.x * 128;
    const uint32_t sb = smem_u32(dsm);

    float acc[2][8][4];
#pragma unroll
    for (int mt = 0; mt < 2; mt++)
#pragma unroll
        for (int nt = 0; nt < 8; nt++)
#pragma unroll
            for (int e = 0; e < 4; e++) acc[mt][nt][e] = 0.f;

    const int a_row = lane & 15;
    const int a_kc  = lane >> 4;
    const int b_row = (lane & 7) + ((lane >> 4) << 3);
    const int b_kc  = (lane >> 3) & 1;

    load_stage(sb, Ahi, Alo, Whi, Wlo, m0, n0, 0, tid);
    CPA_COMMIT();

    for (int k = 0; k < NCHUNK; k++) {
        if (k + 1 < NCHUNK) {
            load_stage(sb + ((k + 1) & 1) * STAGEB, Ahi, Alo, Whi, Wlo,
                       m0, n0, (k + 1) * 32, tid);
            CPA_COMMIT();
            CPA_WAIT(1);
        } else {
            CPA_WAIT(0);
        }
        __syncthreads();

        const uint32_t cs  = sb + (k & 1) * STAGEB;
        const uint32_t sAh = cs, sAl = cs + TILEB, sBh = cs + 2 * TILEB, sBl = cs + 3 * TILEB;

#pragma unroll
        for (int kk = 0; kk < 2; kk++) {
            const int kc = kk * 2;
            uint32_t ah[2][4], al[2][4];
#pragma unroll
            for (int mt = 0; mt < 2; mt++) {
                uint32_t o = sw_off(wm + mt * 16 + a_row, kc + a_kc);
                LDSM_X4(ah[mt][0], ah[mt][1], ah[mt][2], ah[mt][3], sAh + o);
                LDSM_X4(al[mt][0], al[mt][1], al[mt][2], al[mt][3], sAl + o);
            }
#pragma unroll
            for (int ng = 0; ng < 4; ng++) {
                uint32_t bh[4], bl[4];
                uint32_t o = sw_off(wn + ng * 16 + b_row, kc + b_kc);
                LDSM_X4(bh[0], bh[1], bh[2], bh[3], sBh + o);
                LDSM_X4(bl[0], bl[1], bl[2], bl[3], sBl + o);
#pragma unroll
                for (int mt = 0; mt < 2; mt++) {
                    MMA16816(acc[mt][ng * 2 + 0], ah[mt], bh[0], bh[1]);
                    MMA16816(acc[mt][ng * 2 + 0], ah[mt], bl[0], bl[1]);
                    MMA16816(acc[mt][ng * 2 + 0], al[mt], bh[0], bh[1]);
                    MMA16816(acc[mt][ng * 2 + 1], ah[mt], bh[2], bh[3]);
                    MMA16816(acc[mt][ng * 2 + 1], ah[mt], bl[2], bl[3]);
                    MMA16816(acc[mt][ng * 2 + 1], al[mt], bh[2], bh[3]);
                }
            }
        }
        __syncthreads();
    }

    const int erow = lane >> 2;
    const int ecol = (lane & 3) * 2;
#pragma unroll
    for (int mt = 0; mt < 2; mt++) {
#pragma unroll
        for (int nt = 0; nt < 8; nt++) {
            int col = n0 + wn + nt * 8 + ecol;
            float b0 = __ldg(bias + col), b1 = __ldg(bias + col + 1);
            int r0 = m0 + wm + mt * 16 + erow;
            float v00 = acc[mt][nt][0] + b0, v01 = acc[mt][nt][1] + b1;
            float v10 = acc[mt][nt][2] + b0, v11 = acc[mt][nt][3] + b1;
            if (SPLIT) {
                __half h0, l0, h1, l1;
                h_split(v00, h0, l0); h_split(v01, h1, l1);
                *(__half2*)(Chi + (size_t)r0 * Nn + col) = __halves2half2(h0, h1);
                *(__half2*)(Clo + (size_t)r0 * Nn + col) = __halves2half2(l0, l1);
                h_split(v10, h0, l0); h_split(v11, h1, l1);
                *(__half2*)(Chi + (size_t)(r0 + 8) * Nn + col) = __halves2half2(h0, h1);
                *(__half2*)(Clo + (size_t)(r0 + 8) * Nn + col) = __halves2half2(l0, l1);
            } else {
                *(float2*)(C + (size_t)r0 * Nn + col)       = make_float2(v00, v01);
                *(float2*)(C + (size_t)(r0 + 8) * Nn + col) = make_float2(v10, v11);
            }
        }
    }
}

// ---------------- HMMA attention (cp.async ingest of fp16 hi/lo qkv) ----------------
#define KP     256                    // padded keys for S phase
#define VP     208                    // padded keys for AV phase
#define PSTRB  432                    // P row pitch bytes (48 mod 128 -> conflict-free)
#define PSTRH  216
#define SSTR   258
#define A_KH   0
#define A_KL   (A_KH + KP * 128)          // 32768
#define A_VH   (A_KL + KP * 128)          // 65536
#define A_VL   (A_VH + VP * 128)          // 92160
#define A_QH   (A_VL + VP * 128)          // 118784
#define A_QL   (A_QH + 32 * 128)          // 122880
#define A_S    (A_QL + 32 * 128)          // 126976
#define A_PH   (A_S + 32 * SSTR * 4)      // 160000
#define A_PL   (A_PH + 32 * PSTRB)        // 173824
#define A_INV  (A_PL + 32 * PSTRB)        // 187648
#define A_TOT  (A_INV + 128)              // 187776

__global__ __launch_bounds__(256) void attn_hmma_kernel(
    const __half* __restrict__ qhi, const __half* __restrict__ qlo,
    const float* __restrict__ bias,
    __half* __restrict__ aohi, __half* __restrict__ aolo)
{
    extern __shared__ char smb[];
    const uint32_t sb = smem_u32(smb);
    const int b = blockIdx.x / HH;
    const int h = blockIdx.x % HH;
    const int tid = threadIdx.x, lane = tid & 31, wid = tid >> 5;
    const __half* bh_ = qhi + (size_t)b * NT * 2304 + h * 64;
    const __half* bl_ = qlo + (size_t)b * NT * 2304 + h * 64;
    const float* biasH = bias + (size_t)h * NT * NT;

    // zero pads: K rows [NT,KP), V rows [NT,VP), whole P (hi+lo contiguous)
    for (int i = tid; i < ((KP - NT) * 128) / 4; i += 256) {
        ((uint32_t*)(smb + A_KH + NT * 128))[i] = 0;
        ((uint32_t*)(smb + A_KL + NT * 128))[i] = 0;
    }
    for (int i = tid; i < ((VP - NT) * 128) / 4; i += 256) {
        ((uint32_t*)(smb + A_VH + NT * 128))[i] = 0;
        ((uint32_t*)(smb + A_VL + NT * 128))[i] = 0;
    }
    for (int i = tid; i < (2 * 32 * PSTRB) / 4; i += 256)
        ((uint32_t*)(smb + A_PH))[i] = 0;

    // cp.async K and V rows (swizzled 128B rows)
    for (int p = tid; p < NT * 8; p += 256) {
        int row = p >> 3, c = p & 7;
        uint32_t o = swb(row, c);
        size_t goff = (size_t)row * 2304 + 768 + c * 8;
        CPA16(sb + A_KH + o, bh_ + goff);
        CPA16(sb + A_KL + o, bl_ + goff);
        CPA16(sb + A_VH + o, bh_ + goff + 768);
        CPA16(sb + A_VL + o, bl_ + goff + 768);
    }
    CPA_COMMIT();
    CPA_WAIT(0);
    __syncthreads();

    const int a_row16 = lane & 15;
    const int a_kc1   = lane >> 4;
    const int b_row8  = (lane & 7) + ((lane >> 4) << 3);
    const int b_kc1   = (lane >> 3) & 1;

    for (int qt = 0; qt < 7; qt++) {
        const int r0 = qt * 32;
        const int rows = min(32, NT - r0);

        // cp.async Q tile (row-clamped; garbage rows masked later)
        for (int p = tid; p < 32 * 8; p += 256) {
            int r = p >> 3, c = p & 7;
            int gr = (r0 + r < NT) ? (r0 + r) : 0;
            size_t goff = (size_t)gr * 2304 + c * 8;
            uint32_t o = swb(r, c);
            CPA16(sb + A_QH + o, bh_ + goff);
            CPA16(sb + A_QL + o, bl_ + goff);
        }
        CPA_COMMIT();
        CPA_WAIT(0);
        __syncthreads();

        // ---- S = 0.125 * Q K^T + bias ----
        {
            const int wm = (wid & 1) * 16;
            const int wn = (wid >> 1) * 64;
            float acc[8][4];
#pragma unroll
            for (int t = 0; t < 8; t++)
#pragma unroll
                for (int e = 0; e < 4; e++) acc[t][e] = 0.f;

            const int ar = wm + a_row16;
#pragma unroll
            for (int kk = 0; kk < 4; kk++) {
                uint32_t aoff = swb(ar, kk * 2 + a_kc1);
                uint32_t ah[4], al[4];
                LDSM_X4(ah[0], ah[1], ah[2], ah[3], sb + A_QH + aoff);
                LDSM_X4(al[0], al[1], al[2], al[3], sb + A_QL + aoff);
#pragma unroll
                for (int ng = 0; ng < 4; ng++) {
                    uint32_t boff = swb(wn + ng * 16 + b_row8, kk * 2 + b_kc1);
                    uint32_t bh[4], bl[4];
                    LDSM_X4(bh[0], bh[1], bh[2], bh[3], sb + A_KH + boff);
                    LDSM_X4(bl[0], bl[1], bl[2], bl[3], sb + A_KL + boff);
                    MMA16816(acc[ng * 2 + 0], ah, bh[0], bh[1]);
                    MMA16816(acc[ng * 2 + 0], ah, bl[0], bl[1]);
                    MMA16816(acc[ng * 2 + 0], al, bh[0], bh[1]);
                    MMA16816(acc[ng * 2 + 1], ah, bh[2], bh[3]);
                    MMA16816(acc[ng * 2 + 1], ah, bl[2], bl[3]);
                    MMA16816(acc[ng * 2 + 1], al, bh[2], bh[3]);
                }
            }
            const int erow = wm + (lane >> 2);
            const int ecol = (lane & 3) * 2;
            float* S = (float*)(smb + A_S);
#pragma unroll
            for (int nt = 0; nt < 8; nt++) {
                int col = wn + nt * 8 + ecol;
                float b00 = 0.f, b01 = 0.f, b10 = 0.f, b11 = 0.f;
                if (col < NT) {
                    int gr0 = r0 + erow, gr1 = r0 + erow + 8;
                    bool c1 = (col + 1 < NT);
                    if (gr0 < NT) {
                        b00 = biasH[(size_t)gr0 * NT + col];
                        if (c1) b01 = biasH[(size_t)gr0 * NT + col + 1];
                    }
                    if (gr1 < NT) {
                        b10 = biasH[(size_t)gr1 * NT + col];
                        if (c1) b11 = biasH[(size_t)gr1 * NT + col + 1];
                    }
                }
                *(float2*)(S + erow * SSTR + col) =
                    make_float2(acc[nt][0] * 0.125f + b00, acc[nt][1] * 0.125f + b01);
                *(float2*)(S + (erow + 8) * SSTR + col) =
                    make_float2(acc[nt][2] * 0.125f + b10, acc[nt][3] * 0.125f + b11);
            }
        }
        __syncthreads();

        // ---- softmax, emit P hi/lo ----
        {
            float* S = (float*)(smb + A_S);
            __half* PH = (__half*)(smb + A_PH);
            __half* PL = (__half*)(smb + A_PL);
            float* INV = (float*)(smb + A_INV);
#pragma unroll
            for (int i = 0; i < 4; i++) {
                int r = wid * 4 + i;
                if (r < rows) {
                    float m = -3.4e38f;
                    for (int c = lane; c < NT; c += 32) m = fmaxf(m, S[r * SSTR + c]);
#pragma unroll
                    for (int o = 16; o > 0; o >>= 1) m = fmaxf(m, __shfl_xor_sync(0xffffffffu, m, o));
                    float s = 0.f;
                    for (int c = lane; c < NT; c += 32) {
                        float e = __expf(S[r * SSTR + c] - m);
                        s += e;
                        __half eh, el;
                        h_split(e, eh, el);
                        PH[r * PSTRH + c] = eh;
                        PL[r * PSTRH + c] = el;
                    }
#pragma unroll
                    for (int o = 16; o > 0; o >>= 1) s += __shfl_xor_sync(0xffffffffu, s, o);
                    if (lane == 0) INV[r] = 1.f / s;
                }
            }
        }
        __syncthreads();

        // ---- AV = P V (V via ldmatrix.trans) ----
        {
            const int wm = (wid & 1) * 16;
            const int wd = (wid >> 1) * 16;
            float acc[2][4];
#pragma unroll
            for (int t = 0; t < 2; t++)
#pragma unroll
                for (int e = 0; e < 4; e++) acc[t][e] = 0.f;

            const int ar = wm + a_row16;
            const int vch = (wd >> 3) + (lane >> 4);
#pragma unroll
            for (int kk = 0; kk < 13; kk++) {
                uint32_t aoff = (uint32_t)(ar * PSTRB + (kk * 2 + a_kc1) * 16);
                uint32_t ah[4], al[4];
                LDSM_X4(ah[0], ah[1], ah[2], ah[3], sb + A_PH + aoff);
                LDSM_X4(al[0], al[1], al[2], al[3], sb + A_PL + aoff);
                uint32_t boff = swb(kk * 16 + (lane & 15), vch);
                uint32_t bh[4], bl[4];
                LDSM_X4_T(bh[0], bh[1], bh[2], bh[3], sb + A_VH + boff);
                LDSM_X4_T(bl[0], bl[1], bl[2], bl[3], sb + A_VL + boff);
                MMA16816(acc[0], ah, bh[0], bh[1]);
                MMA16816(acc[0], ah, bl[0], bl[1]);
                MMA16816(acc[0], al, bh[0], bh[1]);
                MMA16816(acc[1], ah, bh[2], bh[3]);
                MMA16816(acc[1], ah, bl[2], bl[3]);
                MMA16816(acc[1], al, bh[2], bh[3]);
            }
            const int erow = wm + (lane >> 2);
            const int ec = (lane & 3) * 2;
            float* INV = (float*)(smb + A_INV);
#pragma unroll
            for (int hf = 0; hf < 2; hf++) {
                int rr = erow + hf * 8;
                if (rr < rows) {
                    float inv = INV[rr];
                    size_t gb = ((size_t)b * NT + r0 + rr) * DIM_ + h * 64 + wd;
#pragma unroll
                    for (int nt = 0; nt < 2; nt++) {
                        int d = nt * 8 + ec;
                        __half h0, l0, h1, l1;
                        h_split(acc[nt][hf * 2 + 0] * inv, h0, l0);
                        h_split(acc[nt][hf * 2 + 1] * inv, h1, l1);
                        *(__half2*)(aohi + gb + d) = __halves2half2(h0, h1);
                        *(__half2*)(aolo + gb + d) = __halves2half2(l0, l1);
                    }
                }
            }
        }
        __syncthreads();
    }
}

// ---------------- launch ----------------
extern "C" void kernel_launch(void* const* d_in, const int* in_sizes, int n_in,
                              void* d_out, int out_size)
{
    const float* x      = (const float*)d_in[0];
    const float* qkv_w  = (const float*)d_in[1];
    const float* qkv_b  = (const float*)d_in[2];
    const float* proj_w = (const float*)d_in[3];
    const float* proj_b = (const float*)d_in[4];
    const float* table  = (const float*)d_in[5];
    const int*   relidx = (const int*)d_in[6];
    float* out = (float*)d_out;

    float *p_bias;
    __half *p_qhi, *p_qlo, *p_xhi, *p_xlo, *p_aohi, *p_aolo;
    __half *p_qwhi, *p_qwlo, *p_pwhi, *p_pwlo;
    cudaGetSymbolAddress((void**)&p_qhi,  g_qhi);
    cudaGetSymbolAddress((void**)&p_qlo,  g_qlo);
    cudaGetSymbolAddress((void**)&p_xhi,  g_xhi);
    cudaGetSymbolAddress((void**)&p_xlo,  g_xlo);
    cudaGetSymbolAddress((void**)&p_aohi, g_aohi);
    cudaGetSymbolAddress((void**)&p_aolo, g_aolo);
    cudaGetSymbolAddress((void**)&p_qwhi, g_qwhi);
    cudaGetSymbolAddress((void**)&p_qwlo, g_qwlo);
    cudaGetSymbolAddress((void**)&p_pwhi, g_pwhi);
    cudaGetSymbolAddress((void**)&p_pwlo, g_pwlo);
    cudaGetSymbolAddress((void**)&p_bias, g_bias);

    cudaFuncSetAttribute(attn_hmma_kernel, cudaFuncAttributeMaxDynamicSharedMemorySize, A_TOT);
    cudaFuncSetAttribute(gemm_hmma_kernel<true>,  cudaFuncAttributeMaxDynamicSharedMemorySize, GSMEM);
    cudaFuncSetAttribute(gemm_hmma_kernel<false>, cudaFuncAttributeMaxDynamicSharedMemorySize, GSMEM);

    const int nx = MTOK * DIM_;
    split_kernel<<<(nx + 255) / 256, 256>>>(x, p_xhi, p_xlo, nx);
    split_kernel<<<(2304 * DIM_ + 255) / 256, 256>>>(qkv_w, p_qwhi, p_qwlo, 2304 * DIM_);
    split_kernel<<<(DIM_ * DIM_ + 255) / 256, 256>>>(proj_w, p_pwhi, p_pwlo, DIM_ * DIM_);

    bias_kernel<<<(HH * NT * NT + 255) / 256, 256>>>(table, relidx, p_bias);

    dim3 g1(2304 / 128, MTOK / 128);
    gemm_hmma_kernel<true><<<g1, 256, GSMEM>>>(p_xhi, p_xlo, p_qwhi, p_qwlo, qkv_b,
                                               nullptr, p_qhi, p_qlo, 2304);

    attn_hmma_kernel<<<B_ * HH, 256, A_TOT>>>(p_qhi, p_qlo, p_bias, p_aohi, p_aolo);

    dim3 g2(DIM_ / 128, MTOK / 128);
    gemm_hmma_kernel<false><<<g2, 256, GSMEM>>>(p_aohi, p_aolo, p_pwhi, p_pwlo, proj_b,
                                                out, nullptr, nullptr, DIM_);
}

// round 7
// speedup vs baseline: 2.4647x; 1.0581x over previous
#include <cuda_runtime.h>
#include <cuda_fp16.h>
#include <cstdint>

#define B_   128
#define NT   197
#define HH   12
#define HD   64
#define DIM_ 768
#define MTOK (B_ * NT)          // 25216 = 197*128

// ---------------- scratch ----------------
__device__ __half g_qhi [(long long)MTOK * 2304];   // qkv output hi
__device__ __half g_qlo [(long long)MTOK * 2304];   // qkv output lo
__device__ __half g_xhi [(long long)MTOK * DIM_];
__device__ __half g_xlo [(long long)MTOK * DIM_];
__device__ __half g_aohi[(long long)MTOK * DIM_];
__device__ __half g_aolo[(long long)MTOK * DIM_];
__device__ __half g_qwhi[2304 * DIM_];
__device__ __half g_qwlo[2304 * DIM_];
__device__ __half g_pwhi[DIM_ * DIM_];
__device__ __half g_pwlo[DIM_ * DIM_];
__device__ float  g_bias[HH * NT * NT];

// ---------------- helpers ----------------
__device__ __forceinline__ uint32_t smem_u32(const void* p) {
    uint32_t a;
    asm("{ .reg .u64 t; cvta.to.shared.u64 t, %1; cvt.u32.u64 %0, t; }" : "=r"(a) : "l"(p));
    return a;
}

#define CPA16(dst, src)   asm volatile("cp.async.cg.shared.global [%0], [%1], 16;" :: "r"(dst), "l"(src) : "memory")
#define CPA_COMMIT()      asm volatile("cp.async.commit_group;" ::: "memory")
#define CPA_WAIT(n)       asm volatile("cp.async.wait_group %0;" :: "n"(n) : "memory")

#define LDSM_X4(r0, r1, r2, r3, addr) \
    asm volatile("ldmatrix.sync.aligned.m8n8.x4.shared.b16 {%0,%1,%2,%3}, [%4];" \
        : "=r"(r0), "=r"(r1), "=r"(r2), "=r"(r3) : "r"(addr))

#define LDSM_X4_T(r0, r1, r2, r3, addr) \
    asm volatile("ldmatrix.sync.aligned.m8n8.x4.trans.shared.b16 {%0,%1,%2,%3}, [%4];" \
        : "=r"(r0), "=r"(r1), "=r"(r2), "=r"(r3) : "r"(addr))

#define MMA16816(d, a, b0, b1) \
    asm volatile("mma.sync.aligned.m16n8k16.row.col.f32.f16.f16.f32 " \
        "{%0,%1,%2,%3}, {%4,%5,%6,%7}, {%8,%9}, {%0,%1,%2,%3};" \
        : "+f"((d)[0]), "+f"((d)[1]), "+f"((d)[2]), "+f"((d)[3]) \
        : "r"((a)[0]), "r"((a)[1]), "r"((a)[2]), "r"((a)[3]), "r"(b0), "r"(b1))

// swizzled tile offset for 64B rows (gemm tiles): chunk 0..3
__device__ __forceinline__ uint32_t sw_off(int row, int chunk) {
    return (uint32_t)(row * 64 + ((chunk ^ ((row >> 1) & 3)) << 4));
}
// swizzled offset for 128B rows (attention tiles): chunk 0..7
__device__ __forceinline__ uint32_t swb(int row, int chunk) {
    return (uint32_t)(row * 128 + ((chunk ^ (row & 7)) << 4));
}

static __device__ __forceinline__ void h_split(float v, __half& hi, __half& lo) {
    hi = __float2half_rn(v);
    lo = __float2half_rn(v - __half2float(hi));
}

// ---------------- elementwise fp16 split ----------------
__global__ void split_kernel(const float* __restrict__ in,
                             __half* __restrict__ hi, __half* __restrict__ lo, int n)
{
    int t = blockIdx.x * 256 + threadIdx.x;
    if (t < n) {
        __half h, l;
        h_split(in[t], h, l);
        hi[t] = h; lo[t] = l;
    }
}

// ---------------- bias gather ----------------
__global__ void bias_kernel(const float* __restrict__ table,
                            const int*   __restrict__ idx,
                            float* __restrict__ out)
{
    int t = blockIdx.x * blockDim.x + threadIdx.x;
    if (t < HH * NT * NT) {
        int ij = t % (NT * NT);
        int h  = t / (NT * NT);
        out[t] = table[idx[ij] * HH + h];
    }
}

// ---------------- 3xFP16 mma.sync GEMM, 3-stage pipeline ----------------
#define GK     768
#define NCHUNK 24
#define TILEB  8192
#define STAGEB (4 * TILEB)
#define NSTAGE 3
#define GSMEM  (NSTAGE * STAGEB)       // 96 KB

static __device__ __forceinline__ void load_stage(
    uint32_t sb, const __half* __restrict__ Ahi, const __half* __restrict__ Alo,
    const __half* __restrict__ Whi, const __half* __restrict__ Wlo,
    int m0, int n0, int k0, int tid)
{
#pragma unroll
    for (int j = 0; j < 2; j++) {
        int id = tid + (j << 8);
        int row = id >> 2, c = id & 3;
        uint32_t o = sw_off(row, c);
        size_t ga = (size_t)(m0 + row) * GK + k0 + c * 8;
        size_t gb = (size_t)(n0 + row) * GK + k0 + c * 8;
        CPA16(sb + o,             Ahi + ga);
        CPA16(sb + TILEB + o,     Alo + ga);
        CPA16(sb + 2 * TILEB + o, Whi + gb);
        CPA16(sb + 3 * TILEB + o, Wlo + gb);
    }
}

template<bool SPLIT>
__global__ __launch_bounds__(256, 2)
void gemm_hmma_kernel(const __half* __restrict__ Ahi, const __half* __restrict__ Alo,
                      const __half* __restrict__ Whi, const __half* __restrict__ Wlo,
                      const float* __restrict__ bias, float* __restrict__ C,
                      __half* __restrict__ Chi, __half* __restrict__ Clo, int Nn)
{
    extern __shared__ char dsm[];
    const int tid = threadIdx.x;
    const int lane = tid & 31;
    const int wid = tid >> 5;
    const int wm = (wid & 3) * 32;
    const int wn = (wid >> 2) * 64;
    const int m0 = blockIdx.y * 128;
    const int n0 = blockIdx.x * 128;
    const uint32_t sb = smem_u32(dsm);

    float acc[2][8][4];
#pragma unroll
    for (int mt = 0; mt < 2; mt++)
#pragma unroll
        for (int nt = 0; nt < 8; nt++)
#pragma unroll
            for (int e = 0; e < 4; e++) acc[mt][nt][e] = 0.f;

    const int a_row = lane & 15;
    const int a_kc  = lane >> 4;
    const int b_row = (lane & 7) + ((lane >> 4) << 3);
    const int b_kc  = (lane >> 3) & 1;

    load_stage(sb,          Ahi, Alo, Whi, Wlo, m0, n0, 0,  tid);
    CPA_COMMIT();
    load_stage(sb + STAGEB, Ahi, Alo, Whi, Wlo, m0, n0, 32, tid);
    CPA_COMMIT();

    int st = 0;                       // stage of chunk k
    for (int k = 0; k < NCHUNK; k++) {
        if (k + 1 < NCHUNK) { CPA_WAIT(1); } else { CPA_WAIT(0); }
        __syncthreads();              // guards both data-ready and buffer reuse
        if (k + 2 < NCHUNK) {
            int ls = st + 2; if (ls >= NSTAGE) ls -= NSTAGE;
            load_stage(sb + ls * STAGEB, Ahi, Alo, Whi, Wlo, m0, n0, (k + 2) * 32, tid);
            CPA_COMMIT();
        }

        const uint32_t cs  = sb + st * STAGEB;
        const uint32_t sAh = cs, sAl = cs + TILEB, sBh = cs + 2 * TILEB, sBl = cs + 3 * TILEB;

#pragma unroll
        for (int kk = 0; kk < 2; kk++) {
            const int kc = kk * 2;
            uint32_t ah[2][4], al[2][4];
#pragma unroll
            for (int mt = 0; mt < 2; mt++) {
                uint32_t o = sw_off(wm + mt * 16 + a_row, kc + a_kc);
                LDSM_X4(ah[mt][0], ah[mt][1], ah[mt][2], ah[mt][3], sAh + o);
                LDSM_X4(al[mt][0], al[mt][1], al[mt][2], al[mt][3], sAl + o);
            }
#pragma unroll
            for (int ng = 0; ng < 4; ng++) {
                uint32_t bh[4], bl[4];
                uint32_t o = sw_off(wn + ng * 16 + b_row, kc + b_kc);
                LDSM_X4(bh[0], bh[1], bh[2], bh[3], sBh + o);
                LDSM_X4(bl[0], bl[1], bl[2], bl[3], sBl + o);
#pragma unroll
                for (int mt = 0; mt < 2; mt++) {
                    MMA16816(acc[mt][ng * 2 + 0], ah[mt], bh[0], bh[1]);
                    MMA16816(acc[mt][ng * 2 + 0], ah[mt], bl[0], bl[1]);
                    MMA16816(acc[mt][ng * 2 + 0], al[mt], bh[0], bh[1]);
                    MMA16816(acc[mt][ng * 2 + 1], ah[mt], bh[2], bh[3]);
                    MMA16816(acc[mt][ng * 2 + 1], ah[mt], bl[2], bl[3]);
                    MMA16816(acc[mt][ng * 2 + 1], al[mt], bh[2], bh[3]);
                }
            }
        }
        if (++st == NSTAGE) st = 0;
    }

    const int erow = lane >> 2;
    const int ecol = (lane & 3) * 2;
#pragma unroll
    for (int mt = 0; mt < 2; mt++) {
#pragma unroll
        for (int nt = 0; nt < 8; nt++) {
            int col = n0 + wn + nt * 8 + ecol;
            float b0 = __ldg(bias + col), b1 = __ldg(bias + col + 1);
            int r0 = m0 + wm + mt * 16 + erow;
            float v00 = acc[mt][nt][0] + b0, v01 = acc[mt][nt][1] + b1;
            float v10 = acc[mt][nt][2] + b0, v11 = acc[mt][nt][3] + b1;
            if (SPLIT) {
                __half h0, l0, h1, l1;
                h_split(v00, h0, l0); h_split(v01, h1, l1);
                *(__half2*)(Chi + (size_t)r0 * Nn + col) = __halves2half2(h0, h1);
                *(__half2*)(Clo + (size_t)r0 * Nn + col) = __halves2half2(l0, l1);
                h_split(v10, h0, l0); h_split(v11, h1, l1);
                *(__half2*)(Chi + (size_t)(r0 + 8) * Nn + col) = __halves2half2(h0, h1);
                *(__half2*)(Clo + (size_t)(r0 + 8) * Nn + col) = __halves2half2(l0, l1);
            } else {
                *(float2*)(C + (size_t)r0 * Nn + col)       = make_float2(v00, v01);
                *(float2*)(C + (size_t)(r0 + 8) * Nn + col) = make_float2(v10, v11);
            }
        }
    }
}

// ---------------- HMMA attention (cp.async ingest + Q double-buffer) ----------------
#define KP     256                    // padded keys for S phase
#define VP     208                    // padded keys for AV phase
#define PSTRB  432                    // P row pitch bytes
#define PSTRH  216
#define SSTR   258
#define A_KH   0
#define A_KL   (A_KH + KP * 128)          // 32768
#define A_VH   (A_KL + KP * 128)          // 65536
#define A_VL   (A_VH + VP * 128)          // 92160
#define A_QH   (A_VL + VP * 128)          // 118784 (2 bufs x 4096)
#define A_QL   (A_QH + 2 * 32 * 128)      // 126976 (2 bufs x 4096)
#define A_S    (A_QL + 2 * 32 * 128)      // 135168
#define A_PH   (A_S + 32 * SSTR * 4)      // 168192
#define A_PL   (A_PH + 32 * PSTRB)        // 182016
#define A_INV  (A_PL + 32 * PSTRB)        // 195840
#define A_TOT  (A_INV + 128)              // 195968

__global__ __launch_bounds__(256) void attn_hmma_kernel(
    const __half* __restrict__ qhi, const __half* __restrict__ qlo,
    const float* __restrict__ bias,
    __half* __restrict__ aohi, __half* __restrict__ aolo)
{
    extern __shared__ char smb[];
    const uint32_t sb = smem_u32(smb);
    const int b = blockIdx.x / HH;
    const int h = blockIdx.x % HH;
    const int tid = threadIdx.x, lane = tid & 31, wid = tid >> 5;
    const __half* bh_ = qhi + (size_t)b * NT * 2304 + h * 64;
    const __half* bl_ = qlo + (size_t)b * NT * 2304 + h * 64;
    const float* biasH = bias + (size_t)h * NT * NT;

    // zero pads
    for (int i = tid; i < ((KP - NT) * 128) / 4; i += 256) {
        ((uint32_t*)(smb + A_KH + NT * 128))[i] = 0;
        ((uint32_t*)(smb + A_KL + NT * 128))[i] = 0;
    }
    for (int i = tid; i < ((VP - NT) * 128) / 4; i += 256) {
        ((uint32_t*)(smb + A_VH + NT * 128))[i] = 0;
        ((uint32_t*)(smb + A_VL + NT * 128))[i] = 0;
    }
    for (int i = tid; i < (2 * 32 * PSTRB) / 4; i += 256)
        ((uint32_t*)(smb + A_PH))[i] = 0;

    // cp.async K and V rows (swizzled 128B rows)
    for (int p = tid; p < NT * 8; p += 256) {
        int row = p >> 3, c = p & 7;
        uint32_t o = swb(row, c);
        size_t goff = (size_t)row * 2304 + 768 + c * 8;
        CPA16(sb + A_KH + o, bh_ + goff);
        CPA16(sb + A_KL + o, bl_ + goff);
        CPA16(sb + A_VH + o, bh_ + goff + 768);
        CPA16(sb + A_VL + o, bl_ + goff + 768);
    }
    // Q tile 0 into buffer 0
    for (int p = tid; p < 32 * 8; p += 256) {
        int r = p >> 3, c = p & 7;
        int gr = (r < NT) ? r : 0;
        size_t goff = (size_t)gr * 2304 + c * 8;
        uint32_t o = swb(r, c);
        CPA16(sb + A_QH + o, bh_ + goff);
        CPA16(sb + A_QL + o, bl_ + goff);
    }
    CPA_COMMIT();
    CPA_WAIT(0);
    __syncthreads();

    const int a_row16 = lane & 15;
    const int a_kc1   = lane >> 4;
    const int b_row8  = (lane & 7) + ((lane >> 4) << 3);
    const int b_kc1   = (lane >> 3) & 1;

    for (int qt = 0; qt < 7; qt++) {
        const int r0 = qt * 32;
        const int rows = min(32, NT - r0);
        const uint32_t qbuf = (uint32_t)((qt & 1) * 4096);

        // ---- S = 0.125 * Q K^T + bias ----
        {
            const int wm = (wid & 1) * 16;
            const int wn = (wid >> 1) * 64;
            float acc[8][4];
#pragma unroll
            for (int t = 0; t < 8; t++)
#pragma unroll
                for (int e = 0; e < 4; e++) acc[t][e] = 0.f;

            const int ar = wm + a_row16;
#pragma unroll
            for (int kk = 0; kk < 4; kk++) {
                uint32_t aoff = swb(ar, kk * 2 + a_kc1) + qbuf;
                uint32_t ah[4], al[4];
                LDSM_X4(ah[0], ah[1], ah[2], ah[3], sb + A_QH + aoff);
                LDSM_X4(al[0], al[1], al[2], al[3], sb + A_QL + aoff);
#pragma unroll
                for (int ng = 0; ng < 4; ng++) {
                    uint32_t boff = swb(wn + ng * 16 + b_row8, kk * 2 + b_kc1);
                    uint32_t bh[4], bl[4];
                    LDSM_X4(bh[0], bh[1], bh[2], bh[3], sb + A_KH + boff);
                    LDSM_X4(bl[0], bl[1], bl[2], bl[3], sb + A_KL + boff);
                    MMA16816(acc[ng * 2 + 0], ah, bh[0], bh[1]);
                    MMA16816(acc[ng * 2 + 0], ah, bl[0], bl[1]);
                    MMA16816(acc[ng * 2 + 0], al, bh[0], bh[1]);
                    MMA16816(acc[ng * 2 + 1], ah, bh[2], bh[3]);
                    MMA16816(acc[ng * 2 + 1], ah, bl[2], bl[3]);
                    MMA16816(acc[ng * 2 + 1], al, bh[2], bh[3]);
                }
            }
            const int erow = wm + (lane >> 2);
            const int ecol = (lane & 3) * 2;
            float* S = (float*)(smb + A_S);
#pragma unroll
            for (int nt = 0; nt < 8; nt++) {
                int col = wn + nt * 8 + ecol;
                float b00 = 0.f, b01 = 0.f, b10 = 0.f, b11 = 0.f;
                if (col < NT) {
                    int gr0 = r0 + erow, gr1 = r0 + erow + 8;
                    bool c1 = (col + 1 < NT);
                    if (gr0 < NT) {
                        b00 = biasH[(size_t)gr0 * NT + col];
                        if (c1) b01 = biasH[(size_t)gr0 * NT + col + 1];
                    }
                    if (gr1 < NT) {
                        b10 = biasH[(size_t)gr1 * NT + col];
                        if (c1) b11 = biasH[(size_t)gr1 * NT + col + 1];
                    }
                }
                *(float2*)(S + erow * SSTR + col) =
                    make_float2(acc[nt][0] * 0.125f + b00, acc[nt][1] * 0.125f + b01);
                *(float2*)(S + (erow + 8) * SSTR + col) =
                    make_float2(acc[nt][2] * 0.125f + b10, acc[nt][3] * 0.125f + b11);
            }
        }
        __syncthreads();

        // prefetch next Q tile into the other buffer (overlaps softmax + AV)
        if (qt + 1 < 7) {
            const int nr0 = (qt + 1) * 32;
            const uint32_t nqb = (uint32_t)(((qt + 1) & 1) * 4096);
            for (int p = tid; p < 32 * 8; p += 256) {
                int r = p >> 3, c = p & 7;
                int gr = (nr0 + r < NT) ? (nr0 + r) : 0;
                size_t goff = (size_t)gr * 2304 + c * 8;
                uint32_t o = swb(r, c) + nqb;
                CPA16(sb + A_QH + o, bh_ + goff);
                CPA16(sb + A_QL + o, bl_ + goff);
            }
            CPA_COMMIT();
        }

        // ---- softmax, emit P hi/lo ----
        {
            float* S = (float*)(smb + A_S);
            __half* PH = (__half*)(smb + A_PH);
            __half* PL = (__half*)(smb + A_PL);
            float* INV = (float*)(smb + A_INV);
#pragma unroll
            for (int i = 0; i < 4; i++) {
                int r = wid * 4 + i;
                if (r < rows) {
                    float m = -3.4e38f;
                    for (int c = lane; c < NT; c += 32) m = fmaxf(m, S[r * SSTR + c]);
#pragma unroll
                    for (int o = 16; o > 0; o >>= 1) m = fmaxf(m, __shfl_xor_sync(0xffffffffu, m, o));
                    float s = 0.f;
                    for (int c = lane; c < NT; c += 32) {
                        float e = __expf(S[r * SSTR + c] - m);
                        s += e;
                        __half eh, el;
                        h_split(e, eh, el);
                        PH[r * PSTRH + c] = eh;
                        PL[r * PSTRH + c] = el;
                    }
#pragma unroll
                    for (int o = 16; o > 0; o >>= 1) s += __shfl_xor_sync(0xffffffffu, s, o);
                    if (lane == 0) INV[r] = 1.f / s;
                }
            }
        }
        __syncthreads();

        // ---- AV = P V (V via ldmatrix.trans) ----
        {
            const int wm = (wid & 1) * 16;
            const int wd = (wid >> 1) * 16;
            float acc[2][4];
#pragma unroll
            for (int t = 0; t < 2; t++)
#pragma unroll
                for (int e = 0; e < 4; e++) acc[t][e] = 0.f;

            const int ar = wm + a_row16;
            const int vch = (wd >> 3) + (lane >> 4);
#pragma unroll
            for (int kk = 0; kk < 13; kk++) {
                uint32_t aoff = (uint32_t)(ar * PSTRB + (kk * 2 + a_kc1) * 16);
                uint32_t ah[4], al[4];
                LDSM_X4(ah[0], ah[1], ah[2], ah[3], sb + A_PH + aoff);
                LDSM_X4(al[0], al[1], al[2], al[3], sb + A_PL + aoff);
                uint32_t boff = swb(kk * 16 + (lane & 15), vch);
                uint32_t bh[4], bl[4];
                LDSM_X4_T(bh[0], bh[1], bh[2], bh[3], sb + A_VH + boff);
                LDSM_X4_T(bl[0], bl[1], bl[2], bl[3], sb + A_VL + boff);
                MMA16816(acc[0], ah, bh[0], bh[1]);
                MMA16816(acc[0], ah, bl[0], bl[1]);
                MMA16816(acc[0], al, bh[0], bh[1]);
                MMA16816(acc[1], ah, bh[2], bh[3]);
                MMA16816(acc[1], ah, bl[2], bl[3]);
                MMA16816(acc[1], al, bh[2], bh[3]);
            }
            const int erow = wm + (lane >> 2);
            const int ec = (lane & 3) * 2;
            float* INV = (float*)(smb + A_INV);
#pragma unroll
            for (int hf = 0; hf < 2; hf++) {
                int rr = erow + hf * 8;
                if (rr < rows) {
                    float inv = INV[rr];
                    size_t gb = ((size_t)b * NT + r0 + rr) * DIM_ + h * 64 + wd;
#pragma unroll
                    for (int nt = 0; nt < 2; nt++) {
                        int d = nt * 8 + ec;
                        __half h0, l0, h1, l1;
                        h_split(acc[nt][hf * 2 + 0] * inv, h0, l0);
                        h_split(acc[nt][hf * 2 + 1] * inv, h1, l1);
                        *(__half2*)(aohi + gb + d) = __halves2half2(h0, h1);
                        *(__half2*)(aolo + gb + d) = __halves2half2(l0, l1);
                    }
                }
            }
        }
        if (qt + 1 < 7) { CPA_WAIT(0); }
        __syncthreads();
    }
}

// ---------------- launch ----------------
extern "C" void kernel_launch(void* const* d_in, const int* in_sizes, int n_in,
                              void* d_out, int out_size)
{
    const float* x      = (const float*)d_in[0];
    const float* qkv_w  = (const float*)d_in[1];
    const float* qkv_b  = (const float*)d_in[2];
    const float* proj_w = (const float*)d_in[3];
    const float* proj_b = (const float*)d_in[4];
    const float* table  = (const float*)d_in[5];
    const int*   relidx = (const int*)d_in[6];
    float* out = (float*)d_out;

    float *p_bias;
    __half *p_qhi, *p_qlo, *p_xhi, *p_xlo, *p_aohi, *p_aolo;
    __half *p_qwhi, *p_qwlo, *p_pwhi, *p_pwlo;
    cudaGetSymbolAddress((void**)&p_qhi,  g_qhi);
    cudaGetSymbolAddress((void**)&p_qlo,  g_qlo);
    cudaGetSymbolAddress((void**)&p_xhi,  g_xhi);
    cudaGetSymbolAddress((void**)&p_xlo,  g_xlo);
    cudaGetSymbolAddress((void**)&p_aohi, g_aohi);
    cudaGetSymbolAddress((void**)&p_aolo, g_aolo);
    cudaGetSymbolAddress((void**)&p_qwhi, g_qwhi);
    cudaGetSymbolAddress((void**)&p_qwlo, g_qwlo);
    cudaGetSymbolAddress((void**)&p_pwhi, g_pwhi);
    cudaGetSymbolAddress((void**)&p_pwlo, g_pwlo);
    cudaGetSymbolAddress((void**)&p_bias, g_bias);

    cudaFuncSetAttribute(attn_hmma_kernel, cudaFuncAttributeMaxDynamicSharedMemorySize, A_TOT);
    cudaFuncSetAttribute(gemm_hmma_kernel<true>,  cudaFuncAttributeMaxDynamicSharedMemorySize, GSMEM);
    cudaFuncSetAttribute(gemm_hmma_kernel<false>, cudaFuncAttributeMaxDynamicSharedMemorySize, GSMEM);

    const int nx = MTOK * DIM_;
    split_kernel<<<(nx + 255) / 256, 256>>>(x, p_xhi, p_xlo, nx);
    split_kernel<<<(2304 * DIM_ + 255) / 256, 256>>>(qkv_w, p_qwhi, p_qwlo, 2304 * DIM_);
    split_kernel<<<(DIM_ * DIM_ + 255) / 256, 256>>>(proj_w, p_pwhi, p_pwlo, DIM_ * DIM_);

    bias_kernel<<<(HH * NT * NT + 255) / 256, 256>>>(table, relidx, p_bias);

    dim3 g1(2304 / 128, MTOK / 128);
    gemm_hmma_kernel<true><<<g1, 256, GSMEM>>>(p_xhi, p_xlo, p_qwhi, p_qwlo, qkv_b,
                                               nullptr, p_qhi, p_qlo, 2304);

    attn_hmma_kernel<<<B_ * HH, 256, A_TOT>>>(p_qhi, p_qlo, p_bias, p_aohi, p_aolo);

    dim3 g2(DIM_ / 128, MTOK / 128);
    gemm_hmma_kernel<false><<<g2, 256, GSMEM>>>(p_aohi, p_aolo, p_pwhi, p_pwlo, proj_b,
                                                out, nullptr, nullptr, DIM_);
}